// round 12
// baseline (speedup 1.0000x reference)
#include <cuda_runtime.h>
#include <cuda_bf16.h>
#include <stdint.h>

#define B_ 2
#define H_ 16
#define N_ 2048
#define D_ 64
#define HG 8
#define HL 8
#define W_ 64
#define SCALE 0.125f

__device__ unsigned int d_mb[B_ * 64];
__device__ int d_pos[B_ * N_];
__device__ int d_idx[B_ * N_];
__device__ int d_cnt[B_];
__device__ float d_pgc[(size_t)B_ * HG * N_ * N_];
__device__ __nv_bfloat16 d_kch[(size_t)B_ * HG * N_ * D_];
__device__ __nv_bfloat16 d_kcl[(size_t)B_ * HG * N_ * D_];
__device__ __nv_bfloat16 d_vch[(size_t)B_ * HG * N_ * D_];
__device__ __nv_bfloat16 d_vcl[(size_t)B_ * HG * N_ * D_];

// ---- smem layout (bytes), 256-row CTA ----
#define OQH 0u
#define OQL 36864u
#define OBUF 73728u
#define BUFSTRIDE 73728u
#define BKH 0u
#define BKL 18432u
#define BVH 36864u
#define BVL 55296u
#define OMB 221184u
#define OINV 221696u
#define SMEM_SZ 222720

__device__ __forceinline__ uint32_t smem_u32(const void* p) {
    uint32_t a;
    asm("{ .reg .u64 t; cvta.to.shared.u64 t, %1; cvt.u32.u64 %0, t; }" : "=r"(a) : "l"(p));
    return a;
}
__device__ __forceinline__ void ldsm4(uint32_t a[4], uint32_t addr) {
    asm volatile("ldmatrix.sync.aligned.m8n8.x4.shared.b16 {%0,%1,%2,%3}, [%4];"
                 : "=r"(a[0]), "=r"(a[1]), "=r"(a[2]), "=r"(a[3]) : "r"(addr));
}
__device__ __forceinline__ void ldsm4t(uint32_t a[4], uint32_t addr) {
    asm volatile("ldmatrix.sync.aligned.m8n8.x4.trans.shared.b16 {%0,%1,%2,%3}, [%4];"
                 : "=r"(a[0]), "=r"(a[1]), "=r"(a[2]), "=r"(a[3]) : "r"(addr));
}
__device__ __forceinline__ void mma16816(float c[4], const uint32_t a[4], uint32_t b0, uint32_t b1) {
    asm volatile("mma.sync.aligned.m16n8k16.row.col.f32.bf16.bf16.f32 "
                 "{%0,%1,%2,%3}, {%4,%5,%6,%7}, {%8,%9}, {%0,%1,%2,%3};"
                 : "+f"(c[0]), "+f"(c[1]), "+f"(c[2]), "+f"(c[3])
                 : "r"(a[0]), "r"(a[1]), "r"(a[2]), "r"(a[3]), "r"(b0), "r"(b1));
}
__device__ __forceinline__ uint32_t pack2(float lo, float hi) {
    __nv_bfloat162 t = __floats2bfloat162_rn(lo, hi);
    return *(uint32_t*)&t;
}
__device__ __forceinline__ float bhi(float x) {
    return __bfloat162float(__float2bfloat16(x));
}
__device__ __forceinline__ void split2(float a, float b, uint32_t& hw, uint32_t& lw) {
    __nv_bfloat16 ha = __float2bfloat16(a);
    float fa = __bfloat162float(ha);
    __nv_bfloat16 hb = __float2bfloat16(b);
    float fb = __bfloat162float(hb);
    hw = (uint32_t)__bfloat16_as_ushort(ha) | ((uint32_t)__bfloat16_as_ushort(hb) << 16);
    lw = (uint32_t)__bfloat16_as_ushort(__float2bfloat16(a - fa)) |
         ((uint32_t)__bfloat16_as_ushort(__float2bfloat16(b - fb)) << 16);
}

// ---------------------------------------------------------------------------
// prep: mask dtype detect, bitmask, per-batch compaction map (block-scan)
// ---------------------------------------------------------------------------
__global__ void prep_mask_kernel(const void* __restrict__ mraw) {
    __shared__ int mode;
    __shared__ int wsum[8];
    const int t = threadIdx.x;          // 256 threads
    const int lane = t & 31, wp = t >> 5;
    if (t == 0) {
        const unsigned int* w = (const unsigned int*)mraw;
        bool ii = true, ff = true;
        for (int i = 0; i < 64; i++) {
            unsigned int v = w[i];
            if (v > 1u) ii = false;
            if (v != 0u && v != 0x3F800000u) ff = false;
        }
        mode = ii ? 1 : (ff ? 2 : 0);
    }
    __syncthreads();
    int m = mode;
    if (t < 128) {
        unsigned int w = 0;
        for (int k = 0; k < 32; k++) {
            int idx = t * 32 + k;
            int v;
            if (m == 1)      v = (((const int*)mraw)[idx] != 0);
            else if (m == 2) v = (((const float*)mraw)[idx] != 0.0f);
            else             v = (((const unsigned char*)mraw)[idx] != 0);
            if (v) w |= 1u << k;
        }
        d_mb[t] = w;
    }
    __syncthreads();
    for (int b = 0; b < B_; b++) {
        unsigned int word = d_mb[b * 64 + (t >> 2)];
        unsigned int byte = (word >> ((t & 3) * 8)) & 0xFFu;
        int cnt = __popc(byte);
        int inc = cnt;
#pragma unroll
        for (int o = 1; o < 32; o <<= 1) {
            int v = __shfl_up_sync(0xffffffffu, inc, o);
            if (lane >= o) inc += v;
        }
        if (lane == 31) wsum[wp] = inc;
        __syncthreads();
        int wbase = 0;
#pragma unroll
        for (int i = 0; i < 8; i++) wbase += (i < wp) ? wsum[i] : 0;
        int p = wbase + inc - cnt;
        if (t == 255) d_cnt[b] = wbase + inc;
        for (int k = 0; k < 8; k++) {
            int c = t * 8 + k;
            if ((byte >> k) & 1) {
                d_idx[b * N_ + p] = c;
                d_pos[b * N_ + c] = p;
                p++;
            } else {
                d_pos[b * N_ + c] = 0;
            }
        }
        __syncthreads();
    }
}

// ---------------------------------------------------------------------------
__global__ void __launch_bounds__(256) compact_kv_kernel(const float* __restrict__ K,
                                                         const float* __restrict__ V) {
    const int b = blockIdx.z, h = blockIdx.y, jt = blockIdx.x;
    const int cnt = d_cnt[b];
    const int cnt_pad = (cnt + 127) & ~127;
    const int j0 = jt * 128;
    if (j0 >= cnt_pad) return;
    const size_t obase = (size_t)(b * HG + h) * N_ * D_;
    for (int idx = threadIdx.x; idx < 128 * 16; idx += 256) {
        int r = idx >> 4, c4 = (idx & 15) << 2;
        int j = j0 + r;
        float4 kv = make_float4(0.f, 0.f, 0.f, 0.f);
        float4 vv = make_float4(0.f, 0.f, 0.f, 0.f);
        if (j < cnt) {
            int src = d_idx[b * N_ + j];
            size_t sb = ((size_t)(b * H_ + h) * N_ + src) * D_ + c4;
            kv = *(const float4*)(K + sb);
            vv = *(const float4*)(V + sb);
        }
        size_t off = obase + (size_t)j * D_ + c4;
        uint32_t h01, l01, h23, l23;
        split2(kv.x, kv.y, h01, l01); split2(kv.z, kv.w, h23, l23);
        *(uint2*)(d_kch + off) = make_uint2(h01, h23);
        *(uint2*)(d_kcl + off) = make_uint2(l01, l23);
        split2(vv.x, vv.y, h01, l01); split2(vv.z, vv.w, h23, l23);
        *(uint2*)(d_vch + off) = make_uint2(h01, h23);
        *(uint2*)(d_vcl + off) = make_uint2(l01, l23);
    }
}

__device__ __forceinline__ void loadsplit(const float* __restrict__ src,
                                          __nv_bfloat16* H, __nv_bfloat16* L,
                                          int tid, int n16) {
    for (int idx = tid; idx < n16; idx += 512) {
        int r = idx >> 4, c4 = (idx & 15) << 2;
        float4 v = *(const float4*)(src + r * D_ + c4);
        uint32_t h01, l01, h23, l23;
        split2(v.x, v.y, h01, l01);
        split2(v.z, v.w, h23, l23);
        uint32_t* hp = (uint32_t*)(H + r * 72 + c4);
        uint32_t* lp = (uint32_t*)(L + r * 72 + c4);
        hp[0] = h01; hp[1] = h23;
        lp[0] = l01; lp[1] = l23;
    }
}

__device__ __forceinline__ void loadcopy(const __nv_bfloat16* __restrict__ src,
                                         char* dst, int tid) {
    const uint4* s4 = (const uint4*)src;
    for (int idx = tid; idx < 1024; idx += 512) {
        int r = idx >> 3, c8 = idx & 7;
        uint4 v = s4[r * 8 + c8];
        *(uint4*)(dst + r * 144 + c8 * 16) = v;
    }
}

// ---------------------------------------------------------------------------
// Merged attention + fused normalize tail. blockIdx.y = head (0-7 g, 8-15 l).
// 256 q-rows per CTA, 512 threads, double-buffered K/V.
// ---------------------------------------------------------------------------
__global__ void __launch_bounds__(512, 1)
gattn_kernel(const float* __restrict__ Q, const float* __restrict__ K,
             const float* __restrict__ V, float* __restrict__ outp,
             float* __restrict__ pg, float* __restrict__ pl) {
    extern __shared__ char sm[];
    __nv_bfloat16* QH = (__nv_bfloat16*)(sm + OQH);
    __nv_bfloat16* QL = (__nv_bfloat16*)(sm + OQL);
    float* invS = (float*)(sm + OINV);

    const int b = blockIdx.z, h = blockIdx.y, q0 = blockIdx.x * 256;
    const bool loc = (h >= HG);
    const int tid = threadIdx.x, wq = tid >> 5, lane = tid & 31;
    const int q0w = wq * 16;
    const int l7 = lane & 7, l8 = lane & 8, l15 = lane & 15;
    const int lq = lane >> 2, lc = lane & 3;

    const float* Qp = Q + ((size_t)(b * H_ + h) * N_ + q0) * D_;

    const uint32_t QHa = smem_u32(QH), QLa = smem_u32(QL);
    const uint32_t BUFa = smem_u32(sm + OBUF);
    const uint32_t koff4 = (uint32_t)(l7 * 144 + l8 * 2 + (lane & 16) * 72);
    const uint32_t voff4 = (uint32_t)(l15 * 144 + ((lane & 16) ? 18432u : 0u));

    const int qa = q0 + q0w + lq;
    const int qb = qa + 8;
    const int qw0 = q0 + q0w;

    float O[8][4];
#pragma unroll
    for (int n = 0; n < 8; n++)
#pragma unroll
        for (int e = 0; e < 4; e++) O[n][e] = 0.0f;
    float lpa = 0.0f, lpb = 0.0f;

    if (!loc) {
        // ================= GLOBAL (compacted keys) =================
        const int cnt = d_cnt[b];
        const int ktn = (cnt + 127) >> 7;
        const __nv_bfloat16* Kh = d_kch + (size_t)(b * HG + h) * N_ * D_;
        const __nv_bfloat16* Kl = d_kcl + (size_t)(b * HG + h) * N_ * D_;
        const __nv_bfloat16* Vh = d_vch + (size_t)(b * HG + h) * N_ * D_;
        const __nv_bfloat16* Vl = d_vcl + (size_t)(b * HG + h) * N_ * D_;
        float* pra = d_pgc + ((size_t)(b * HG + h) * N_ + qa) * N_;
        float* prb = pra + (size_t)8 * N_;

        loadsplit(Qp, QH, QL, tid, 4096);
        {
            char* bb = sm + OBUF;
            loadcopy(Kh, bb + BKH, tid);
            loadcopy(Kl, bb + BKL, tid);
            loadcopy(Vh, bb + BVH, tid);
            loadcopy(Vl, bb + BVL, tid);
        }
        __syncthreads();

        uint32_t aQH[4][4], aQL[4][4];
#pragma unroll
        for (int kk = 0; kk < 4; kk++) {
            uint32_t qo = (uint32_t)((q0w + l15) * 144 + kk * 32 + ((lane & 16) ? 16 : 0));
            ldsm4(aQH[kk], QHa + qo);
            ldsm4(aQL[kk], QLa + qo);
        }

        int cur = 0;
        for (int kt = 0; kt < ktn; kt++) {
            if (kt + 1 < ktn) {
                char* bb = sm + OBUF + (uint32_t)(cur ^ 1) * BUFSTRIDE;
                size_t t0 = (size_t)(kt + 1) * 128 * D_;
                loadcopy(Kh + t0, bb + BKH, tid);
                loadcopy(Kl + t0, bb + BKL, tid);
                loadcopy(Vh + t0, bb + BVH, tid);
                loadcopy(Vl + t0, bb + BVL, tid);
            }
            const uint32_t KHa = BUFa + (uint32_t)cur * BUFSTRIDE;
            const uint32_t KLa = KHa + BKL;
            const uint32_t VHa = KHa + BVH;

#pragma unroll
            for (int j = 0; j < 8; j++) {
                const int ct = kt * 128 + j * 16 + 2 * lc;
                float c0[4] = {0, 0, 0, 0}, c1[4] = {0, 0, 0, 0};
                uint32_t jo = (uint32_t)j * 2304u + koff4;
#pragma unroll
                for (int kk = 0; kk < 4; kk++) {
                    uint32_t bH[4], bL[4];
                    ldsm4(bH, KHa + jo + kk * 32);
                    ldsm4(bL, KLa + jo + kk * 32);
                    mma16816(c0, aQH[kk], bH[0], bH[1]);
                    mma16816(c0, aQH[kk], bL[0], bL[1]);
                    mma16816(c0, aQL[kk], bH[0], bH[1]);
                    mma16816(c1, aQH[kk], bH[2], bH[3]);
                    mma16816(c1, aQH[kk], bL[2], bL[3]);
                    mma16816(c1, aQL[kk], bH[2], bH[3]);
                }
                bool m0 = (ct < cnt), m1 = (ct + 1 < cnt);
                bool m8 = (ct + 8 < cnt), m9 = (ct + 9 < cnt);
                float p0a0 = m0 ? __expf(c0[0] * SCALE) : 0.0f;
                float p0a1 = m1 ? __expf(c0[1] * SCALE) : 0.0f;
                float p0b0 = m0 ? __expf(c0[2] * SCALE) : 0.0f;
                float p0b1 = m1 ? __expf(c0[3] * SCALE) : 0.0f;
                float p1a0 = m8 ? __expf(c1[0] * SCALE) : 0.0f;
                float p1a1 = m9 ? __expf(c1[1] * SCALE) : 0.0f;
                float p1b0 = m8 ? __expf(c1[2] * SCALE) : 0.0f;
                float p1b1 = m9 ? __expf(c1[3] * SCALE) : 0.0f;

                lpa += (p0a0 + p0a1) + (p1a0 + p1a1);
                lpb += (p0b0 + p0b1) + (p1b0 + p1b1);

                *(float2*)(pra + ct)     = make_float2(p0a0, p0a1);
                *(float2*)(pra + ct + 8) = make_float2(p1a0, p1a1);
                *(float2*)(prb + ct)     = make_float2(p0b0, p0b1);
                *(float2*)(prb + ct + 8) = make_float2(p1b0, p1b1);

                uint32_t paH[4], paL[4];
                paH[0] = pack2(bhi(p0a0), bhi(p0a1));
                paH[1] = pack2(bhi(p0b0), bhi(p0b1));
                paH[2] = pack2(bhi(p1a0), bhi(p1a1));
                paH[3] = pack2(bhi(p1b0), bhi(p1b1));
                paL[0] = pack2(p0a0 - bhi(p0a0), p0a1 - bhi(p0a1));
                paL[1] = pack2(p0b0 - bhi(p0b0), p0b1 - bhi(p0b1));
                paL[2] = pack2(p1a0 - bhi(p1a0), p1a1 - bhi(p1a1));
                paL[3] = pack2(p1b0 - bhi(p1b0), p1b1 - bhi(p1b1));

                uint32_t vj = (uint32_t)j * 2304u + voff4;
#pragma unroll
                for (int n = 0; n < 8; n++) {
                    uint32_t v4[4];
                    ldsm4t(v4, VHa + vj + n * 16);
                    mma16816(O[n], paH, v4[0], v4[1]);
                    mma16816(O[n], paH, v4[2], v4[3]);
                    mma16816(O[n], paL, v4[0], v4[1]);
                }
            }
            __syncthreads();
            cur ^= 1;
        }
    } else {
        // ================= LOCAL (banded) =================
        unsigned int* mbS = (unsigned int*)(sm + OMB);
        const int hy = h - HG;
        const float* Kp = K + ((size_t)(b * H_ + h)) * N_ * D_;
        const float* Vp = V + ((size_t)(b * H_ + h)) * N_ * D_;
        float* prowbase = pl + ((size_t)(b * HL + hy) * N_ + q0) * N_;
        float* pra = prowbase + (size_t)(q0w + lq) * N_;
        float* prb = pra + (size_t)8 * N_;

        int klo = q0 - W_; if (klo < 0) klo = 0;
        int khi = q0 + 255 + W_; if (khi > N_ - 1) khi = N_ - 1;
        const int ktlo = klo >> 7, kthi = khi >> 7;
        {
            float4 z = make_float4(0.f, 0.f, 0.f, 0.f);
            for (int kt = 0; kt < 16; kt++) {
                if (kt >= ktlo && kt <= kthi) continue;
                for (int idx = tid; idx < 256 * 32; idx += 512) {
                    int r = idx >> 5, c4 = (idx & 31) << 2;
                    *(float4*)(prowbase + (size_t)r * N_ + kt * 128 + c4) = z;
                }
            }
        }

        if (tid < 64) mbS[tid] = d_mb[b * 64 + tid];
        loadsplit(Qp, QH, QL, tid, 4096);
        {
            char* bb = sm + OBUF;
            loadsplit(Kp + (size_t)ktlo * 128 * D_, (__nv_bfloat16*)(bb + BKH),
                      (__nv_bfloat16*)(bb + BKL), tid, 2048);
            loadsplit(Vp + (size_t)ktlo * 128 * D_, (__nv_bfloat16*)(bb + BVH),
                      (__nv_bfloat16*)(bb + BVL), tid, 2048);
        }
        __syncthreads();

        uint32_t aQH[4][4], aQL[4][4];
#pragma unroll
        for (int kk = 0; kk < 4; kk++) {
            uint32_t qo = (uint32_t)((q0w + l15) * 144 + kk * 32 + ((lane & 16) ? 16 : 0));
            ldsm4(aQH[kk], QHa + qo);
            ldsm4(aQL[kk], QLa + qo);
        }

        int cur = 0;
        for (int kt = ktlo; kt <= kthi; kt++) {
            if (kt < kthi) {
                char* bb = sm + OBUF + (uint32_t)(cur ^ 1) * BUFSTRIDE;
                loadsplit(Kp + (size_t)(kt + 1) * 128 * D_, (__nv_bfloat16*)(bb + BKH),
                          (__nv_bfloat16*)(bb + BKL), tid, 2048);
                loadsplit(Vp + (size_t)(kt + 1) * 128 * D_, (__nv_bfloat16*)(bb + BVH),
                          (__nv_bfloat16*)(bb + BVL), tid, 2048);
            }
            const uint32_t KHa = BUFa + (uint32_t)cur * BUFSTRIDE;
            const uint32_t KLa = KHa + BKL;
            const uint32_t VHa = KHa + BVH;

            unsigned int mw[4];
#pragma unroll
            for (int i = 0; i < 4; i++) mw[i] = mbS[kt * 4 + i];
#pragma unroll
            for (int j = 0; j < 8; j++) {
                const int k0j = kt * 128 + j * 16;
                const int ct = k0j + 2 * lc;
                if (!((k0j <= qw0 + 79) && (k0j + 15 >= qw0 - 64))) {
                    float2 z2 = make_float2(0.f, 0.f);
                    *(float2*)(pra + ct) = z2; *(float2*)(pra + ct + 8) = z2;
                    *(float2*)(prb + ct) = z2; *(float2*)(prb + ct + 8) = z2;
                    continue;
                }
                float c0[4] = {0, 0, 0, 0}, c1[4] = {0, 0, 0, 0};
                uint32_t jo = (uint32_t)j * 2304u + koff4;
#pragma unroll
                for (int kk = 0; kk < 4; kk++) {
                    uint32_t bH[4], bL[4];
                    ldsm4(bH, KHa + jo + kk * 32);
                    ldsm4(bL, KLa + jo + kk * 32);
                    mma16816(c0, aQH[kk], bH[0], bH[1]);
                    mma16816(c0, aQH[kk], bL[0], bL[1]);
                    mma16816(c0, aQL[kk], bH[0], bH[1]);
                    mma16816(c1, aQH[kk], bH[2], bH[3]);
                    mma16816(c1, aQH[kk], bL[2], bL[3]);
                    mma16816(c1, aQL[kk], bH[2], bH[3]);
                }
                unsigned int w = mw[j >> 1];
                int sh = (j & 1) * 16 + 2 * lc;
                bool m0 = (w >> sh) & 1, m1 = (w >> (sh + 1)) & 1;
                bool m8 = (w >> (sh + 8)) & 1, m9 = (w >> (sh + 9)) & 1;
                bool ba0 = ((unsigned)(ct - qa + 64) <= 128u);
                bool ba1 = ((unsigned)(ct + 1 - qa + 64) <= 128u);
                bool bb0 = ((unsigned)(ct - qb + 64) <= 128u);
                bool bb1 = ((unsigned)(ct + 1 - qb + 64) <= 128u);
                bool ba8 = ((unsigned)(ct + 8 - qa + 64) <= 128u);
                bool ba9 = ((unsigned)(ct + 9 - qa + 64) <= 128u);
                bool bb8 = ((unsigned)(ct + 8 - qb + 64) <= 128u);
                bool bb9 = ((unsigned)(ct + 9 - qb + 64) <= 128u);

                float p0a0 = (m0 && ba0) ? __expf(c0[0] * SCALE) : 0.0f;
                float p0a1 = (m1 && ba1) ? __expf(c0[1] * SCALE) : 0.0f;
                float p0b0 = (m0 && bb0) ? __expf(c0[2] * SCALE) : 0.0f;
                float p0b1 = (m1 && bb1) ? __expf(c0[3] * SCALE) : 0.0f;
                float p1a0 = (m8 && ba8) ? __expf(c1[0] * SCALE) : 0.0f;
                float p1a1 = (m9 && ba9) ? __expf(c1[1] * SCALE) : 0.0f;
                float p1b0 = (m8 && bb8) ? __expf(c1[2] * SCALE) : 0.0f;
                float p1b1 = (m9 && bb9) ? __expf(c1[3] * SCALE) : 0.0f;

                lpa += (p0a0 + p0a1) + (p1a0 + p1a1);
                lpb += (p0b0 + p0b1) + (p1b0 + p1b1);

                *(float2*)(pra + ct)     = make_float2(p0a0, p0a1);
                *(float2*)(pra + ct + 8) = make_float2(p1a0, p1a1);
                *(float2*)(prb + ct)     = make_float2(p0b0, p0b1);
                *(float2*)(prb + ct + 8) = make_float2(p1b0, p1b1);

                uint32_t paH[4], paL[4];
                paH[0] = pack2(bhi(p0a0), bhi(p0a1));
                paH[1] = pack2(bhi(p0b0), bhi(p0b1));
                paH[2] = pack2(bhi(p1a0), bhi(p1a1));
                paH[3] = pack2(bhi(p1b0), bhi(p1b1));
                paL[0] = pack2(p0a0 - bhi(p0a0), p0a1 - bhi(p0a1));
                paL[1] = pack2(p0b0 - bhi(p0b0), p0b1 - bhi(p0b1));
                paL[2] = pack2(p1a0 - bhi(p1a0), p1a1 - bhi(p1a1));
                paL[3] = pack2(p1b0 - bhi(p1b0), p1b1 - bhi(p1b1));

                uint32_t vj = (uint32_t)j * 2304u + voff4;
#pragma unroll
                for (int n = 0; n < 8; n++) {
                    uint32_t v4[4];
                    ldsm4t(v4, VHa + vj + n * 16);
                    mma16816(O[n], paH, v4[0], v4[1]);
                    mma16816(O[n], paH, v4[2], v4[3]);
                    mma16816(O[n], paL, v4[0], v4[1]);
                }
            }
            __syncthreads();
            cur ^= 1;
        }
    }

    lpa += __shfl_xor_sync(0xffffffffu, lpa, 1);
    lpa += __shfl_xor_sync(0xffffffffu, lpa, 2);
    lpb += __shfl_xor_sync(0xffffffffu, lpb, 1);
    lpb += __shfl_xor_sync(0xffffffffu, lpb, 2);
    const float invla = (lpa > 0.0f) ? 1.0f / lpa : 0.0f;
    const float invlb = (lpb > 0.0f) ? 1.0f / lpb : 0.0f;

    if (lc == 0) {
        invS[q0w + lq] = invla;
        invS[q0w + lq + 8] = invlb;
    }

    // O epilogue
    float* oa = outp + ((size_t)(b * H_ + h) * N_ + qa) * D_;
    float* ob = outp + ((size_t)(b * H_ + h) * N_ + qb) * D_;
#pragma unroll
    for (int n = 0; n < 8; n++) {
        *(float2*)(oa + n * 8 + 2 * lc) = make_float2(O[n][0] * invla, O[n][1] * invla);
        *(float2*)(ob + n * 8 + 2 * lc) = make_float2(O[n][2] * invlb, O[n][3] * invlb);
    }

    // fused tail: __syncthreads fences this CTA's gmem p' writes + invS
    __syncthreads();
    if (!loc) {
        // expand + normalize this CTA's 256 pg rows. 512 threads x float4 = 2048 cols.
        const int c4 = tid << 2;
        const int4 pp = *(const int4*)(d_pos + b * N_ + c4);
        const unsigned int wb = d_mb[b * 64 + (c4 >> 5)];
        const int sh = c4 & 31;
        const bool e0 = (wb >> sh) & 1, e1 = (wb >> (sh + 1)) & 1;
        const bool e2 = (wb >> (sh + 2)) & 1, e3 = (wb >> (sh + 3)) & 1;
        const float* srcb = d_pgc + ((size_t)(b * HG + h) * N_ + q0) * N_;
        float* dstb = pg + ((size_t)(b * HG + h) * N_ + q0) * N_;
#pragma unroll 2
        for (int r = 0; r < 256; r++) {
            const float* s = srcb + (size_t)r * N_;
            const float iv = invS[r];
            float4 o;
            o.x = e0 ? s[pp.x] * iv : 0.0f;
            o.y = e1 ? s[pp.y] * iv : 0.0f;
            o.z = e2 ? s[pp.z] * iv : 0.0f;
            o.w = e3 ? s[pp.w] * iv : 0.0f;
            *(float4*)(dstb + (size_t)r * N_ + c4) = o;
        }
    } else {
        // scale this CTA's 256 pl bands in place. 4 rows per iter, 128 threads/row.
        const int hy = h - HG;
        float* plb = pl + ((size_t)(b * HL + hy) * N_ + q0) * N_;
        const int rsub = tid >> 7;          // 0..3
        const int csub = tid & 127;
        for (int base = 0; base < 256; base += 4) {
            int r = base + rsub;
            int q = q0 + r;
            float s = invS[r];
            int lo = q - W_; if (lo < 0) lo = 0;
            int hi = q + W_; if (hi > N_ - 1) hi = N_ - 1;
            float* p = plb + (size_t)r * N_;
            for (int c = lo + csub; c <= hi; c += 128)
                p[c] *= s;
        }
    }
}

// ---------------------------------------------------------------------------
extern "C" void kernel_launch(void* const* d_in, const int* in_sizes, int n_in,
                              void* d_out, int out_size) {
    const float* Q = (const float*)d_in[0];
    const float* K = (const float*)d_in[1];
    const float* V = (const float*)d_in[2];
    const void* mask = d_in[3];

    float* out = (float*)d_out;
    float* pg = out + (size_t)B_ * H_ * N_ * D_;
    float* pl = pg + (size_t)B_ * HG * N_ * N_;

    static int attr_set = 0;
    if (!attr_set) {
        cudaFuncSetAttribute(gattn_kernel, cudaFuncAttributeMaxDynamicSharedMemorySize, SMEM_SZ);
        attr_set = 1;
    }

    prep_mask_kernel<<<1, 256>>>(mask);
    compact_kv_kernel<<<dim3(16, HG, B_), 256>>>(K, V);

    gattn_kernel<<<dim3(N_ / 256, H_, B_), 512, SMEM_SZ>>>(Q, K, V, out, pg, pl);
}

// round 14
// speedup vs baseline: 1.3488x; 1.3488x over previous
#include <cuda_runtime.h>
#include <cuda_bf16.h>
#include <stdint.h>

#define B_ 2
#define H_ 16
#define N_ 2048
#define D_ 64
#define HG 8
#define HL 8
#define W_ 64
#define SCALE 0.125f

__device__ unsigned int d_mb[B_ * 64];
__device__ float d_linv[B_ * H_ * N_];
__device__ int d_pos[B_ * N_];
__device__ int d_idx[B_ * N_];
__device__ int d_cnt[B_];
__device__ float d_pgc[(size_t)B_ * HG * N_ * N_];
__device__ __nv_bfloat16 d_kch[(size_t)B_ * HG * N_ * D_];
__device__ __nv_bfloat16 d_kcl[(size_t)B_ * HG * N_ * D_];
__device__ __nv_bfloat16 d_vch[(size_t)B_ * HG * N_ * D_];
__device__ __nv_bfloat16 d_vcl[(size_t)B_ * HG * N_ * D_];

// ---- smem layout (bytes), 256-row CTA ----
#define OQH 0u
#define OQL 36864u
#define OBUF 73728u
#define BUFSTRIDE 73728u
#define BKH 0u
#define BKL 18432u
#define BVH 36864u
#define BVL 55296u
#define OMB 221184u
#define SMEM_SZ 221696

__device__ __forceinline__ uint32_t smem_u32(const void* p) {
    uint32_t a;
    asm("{ .reg .u64 t; cvta.to.shared.u64 t, %1; cvt.u32.u64 %0, t; }" : "=r"(a) : "l"(p));
    return a;
}
__device__ __forceinline__ void ldsm4(uint32_t a[4], uint32_t addr) {
    asm volatile("ldmatrix.sync.aligned.m8n8.x4.shared.b16 {%0,%1,%2,%3}, [%4];"
                 : "=r"(a[0]), "=r"(a[1]), "=r"(a[2]), "=r"(a[3]) : "r"(addr));
}
__device__ __forceinline__ void ldsm4t(uint32_t a[4], uint32_t addr) {
    asm volatile("ldmatrix.sync.aligned.m8n8.x4.trans.shared.b16 {%0,%1,%2,%3}, [%4];"
                 : "=r"(a[0]), "=r"(a[1]), "=r"(a[2]), "=r"(a[3]) : "r"(addr));
}
__device__ __forceinline__ void mma16816(float c[4], const uint32_t a[4], uint32_t b0, uint32_t b1) {
    asm volatile("mma.sync.aligned.m16n8k16.row.col.f32.bf16.bf16.f32 "
                 "{%0,%1,%2,%3}, {%4,%5,%6,%7}, {%8,%9}, {%0,%1,%2,%3};"
                 : "+f"(c[0]), "+f"(c[1]), "+f"(c[2]), "+f"(c[3])
                 : "r"(a[0]), "r"(a[1]), "r"(a[2]), "r"(a[3]), "r"(b0), "r"(b1));
}
__device__ __forceinline__ uint32_t pack2(float lo, float hi) {
    __nv_bfloat162 t = __floats2bfloat162_rn(lo, hi);
    return *(uint32_t*)&t;
}
__device__ __forceinline__ float bhi(float x) {
    return __bfloat162float(__float2bfloat16(x));
}
__device__ __forceinline__ void split2(float a, float b, uint32_t& hw, uint32_t& lw) {
    __nv_bfloat16 ha = __float2bfloat16(a);
    float fa = __bfloat162float(ha);
    __nv_bfloat16 hb = __float2bfloat16(b);
    float fb = __bfloat162float(hb);
    hw = (uint32_t)__bfloat16_as_ushort(ha) | ((uint32_t)__bfloat16_as_ushort(hb) << 16);
    lw = (uint32_t)__bfloat16_as_ushort(__float2bfloat16(a - fa)) |
         ((uint32_t)__bfloat16_as_ushort(__float2bfloat16(b - fb)) << 16);
}

// ---------------------------------------------------------------------------
// prep: mask dtype detect, bitmask, per-batch compaction map (block-scan)
// ---------------------------------------------------------------------------
__global__ void prep_mask_kernel(const void* __restrict__ mraw) {
    __shared__ int mode;
    __shared__ int wsum[8];
    const int t = threadIdx.x;          // 256 threads
    const int lane = t & 31, wp = t >> 5;
    if (t == 0) {
        const unsigned int* w = (const unsigned int*)mraw;
        bool ii = true, ff = true;
        for (int i = 0; i < 64; i++) {
            unsigned int v = w[i];
            if (v > 1u) ii = false;
            if (v != 0u && v != 0x3F800000u) ff = false;
        }
        mode = ii ? 1 : (ff ? 2 : 0);
    }
    __syncthreads();
    int m = mode;
    if (t < 128) {
        unsigned int w = 0;
        for (int k = 0; k < 32; k++) {
            int idx = t * 32 + k;
            int v;
            if (m == 1)      v = (((const int*)mraw)[idx] != 0);
            else if (m == 2) v = (((const float*)mraw)[idx] != 0.0f);
            else             v = (((const unsigned char*)mraw)[idx] != 0);
            if (v) w |= 1u << k;
        }
        d_mb[t] = w;
    }
    __syncthreads();
    for (int b = 0; b < B_; b++) {
        unsigned int word = d_mb[b * 64 + (t >> 2)];
        unsigned int byte = (word >> ((t & 3) * 8)) & 0xFFu;
        int cnt = __popc(byte);
        int inc = cnt;
#pragma unroll
        for (int o = 1; o < 32; o <<= 1) {
            int v = __shfl_up_sync(0xffffffffu, inc, o);
            if (lane >= o) inc += v;
        }
        if (lane == 31) wsum[wp] = inc;
        __syncthreads();
        int wbase = 0;
#pragma unroll
        for (int i = 0; i < 8; i++) wbase += (i < wp) ? wsum[i] : 0;
        int p = wbase + inc - cnt;
        if (t == 255) d_cnt[b] = wbase + inc;
        for (int k = 0; k < 8; k++) {
            int c = t * 8 + k;
            if ((byte >> k) & 1) {
                d_idx[b * N_ + p] = c;
                d_pos[b * N_ + c] = p;
                p++;
            } else {
                d_pos[b * N_ + c] = 0;
            }
        }
        __syncthreads();
    }
}

// ---------------------------------------------------------------------------
__global__ void __launch_bounds__(256) compact_kv_kernel(const float* __restrict__ K,
                                                         const float* __restrict__ V) {
    const int b = blockIdx.z, h = blockIdx.y, jt = blockIdx.x;
    const int cnt = d_cnt[b];
    const int cnt_pad = (cnt + 127) & ~127;
    const int j0 = jt * 128;
    if (j0 >= cnt_pad) return;
    const size_t obase = (size_t)(b * HG + h) * N_ * D_;
    for (int idx = threadIdx.x; idx < 128 * 16; idx += 256) {
        int r = idx >> 4, c4 = (idx & 15) << 2;
        int j = j0 + r;
        float4 kv = make_float4(0.f, 0.f, 0.f, 0.f);
        float4 vv = make_float4(0.f, 0.f, 0.f, 0.f);
        if (j < cnt) {
            int src = d_idx[b * N_ + j];
            size_t sb = ((size_t)(b * H_ + h) * N_ + src) * D_ + c4;
            kv = *(const float4*)(K + sb);
            vv = *(const float4*)(V + sb);
        }
        size_t off = obase + (size_t)j * D_ + c4;
        uint32_t h01, l01, h23, l23;
        split2(kv.x, kv.y, h01, l01); split2(kv.z, kv.w, h23, l23);
        *(uint2*)(d_kch + off) = make_uint2(h01, h23);
        *(uint2*)(d_kcl + off) = make_uint2(l01, l23);
        split2(vv.x, vv.y, h01, l01); split2(vv.z, vv.w, h23, l23);
        *(uint2*)(d_vch + off) = make_uint2(h01, h23);
        *(uint2*)(d_vcl + off) = make_uint2(l01, l23);
    }
}

__device__ __forceinline__ void loadsplit(const float* __restrict__ src,
                                          __nv_bfloat16* H, __nv_bfloat16* L,
                                          int tid, int n16) {
    for (int idx = tid; idx < n16; idx += 512) {
        int r = idx >> 4, c4 = (idx & 15) << 2;
        float4 v = *(const float4*)(src + r * D_ + c4);
        uint32_t h01, l01, h23, l23;
        split2(v.x, v.y, h01, l01);
        split2(v.z, v.w, h23, l23);
        uint32_t* hp = (uint32_t*)(H + r * 72 + c4);
        uint32_t* lp = (uint32_t*)(L + r * 72 + c4);
        hp[0] = h01; hp[1] = h23;
        lp[0] = l01; lp[1] = l23;
    }
}

__device__ __forceinline__ void loadcopy(const __nv_bfloat16* __restrict__ src,
                                         char* dst, int tid) {
    const uint4* s4 = (const uint4*)src;
    for (int idx = tid; idx < 1024; idx += 512) {
        int r = idx >> 3, c8 = idx & 7;
        uint4 v = s4[r * 8 + c8];
        *(uint4*)(dst + r * 144 + c8 * 16) = v;
    }
}

// ---------------------------------------------------------------------------
// Merged attention (R11 structure): blockIdx.y = head (0-7 global, 8-15 local)
// 256 q-rows per CTA, 512 threads, double-buffered K/V.
// Local CTAs rescale their own pl bands in the tail (single multiply).
// ---------------------------------------------------------------------------
__global__ void __launch_bounds__(512, 1)
gattn_kernel(const float* __restrict__ Q, const float* __restrict__ K,
             const float* __restrict__ V, float* __restrict__ outp,
             float* __restrict__ pl) {
    extern __shared__ char sm[];
    __nv_bfloat16* QH = (__nv_bfloat16*)(sm + OQH);
    __nv_bfloat16* QL = (__nv_bfloat16*)(sm + OQL);

    const int b = blockIdx.z, h = blockIdx.y, q0 = blockIdx.x * 256;
    const bool loc = (h >= HG);
    const int tid = threadIdx.x, wq = tid >> 5, lane = tid & 31;
    const int q0w = wq * 16;
    const int l7 = lane & 7, l8 = lane & 8, l15 = lane & 15;
    const int lq = lane >> 2, lc = lane & 3;

    const float* Qp = Q + ((size_t)(b * H_ + h) * N_ + q0) * D_;

    const uint32_t QHa = smem_u32(QH), QLa = smem_u32(QL);
    const uint32_t BUFa = smem_u32(sm + OBUF);
    const uint32_t koff4 = (uint32_t)(l7 * 144 + l8 * 2 + (lane & 16) * 72);
    const uint32_t voff4 = (uint32_t)(l15 * 144 + ((lane & 16) ? 18432u : 0u));

    const int qa = q0 + q0w + lq;
    const int qb = qa + 8;
    const int qw0 = q0 + q0w;

    float O[8][4];
#pragma unroll
    for (int n = 0; n < 8; n++)
#pragma unroll
        for (int e = 0; e < 4; e++) O[n][e] = 0.0f;
    float lpa = 0.0f, lpb = 0.0f;

    float* pra_l = 0; float* prb_l = 0;   // local-head row pointers (for tail)

    if (!loc) {
        // ================= GLOBAL (compacted keys) =================
        const int cnt = d_cnt[b];
        const int ktn = (cnt + 127) >> 7;
        const __nv_bfloat16* Kh = d_kch + (size_t)(b * HG + h) * N_ * D_;
        const __nv_bfloat16* Kl = d_kcl + (size_t)(b * HG + h) * N_ * D_;
        const __nv_bfloat16* Vh = d_vch + (size_t)(b * HG + h) * N_ * D_;
        const __nv_bfloat16* Vl = d_vcl + (size_t)(b * HG + h) * N_ * D_;
        float* pra = d_pgc + ((size_t)(b * HG + h) * N_ + qa) * N_;
        float* prb = pra + (size_t)8 * N_;

        loadsplit(Qp, QH, QL, tid, 4096);
        {
            char* bb = sm + OBUF;
            loadcopy(Kh, bb + BKH, tid);
            loadcopy(Kl, bb + BKL, tid);
            loadcopy(Vh, bb + BVH, tid);
            loadcopy(Vl, bb + BVL, tid);
        }
        __syncthreads();

        uint32_t aQH[4][4], aQL[4][4];
#pragma unroll
        for (int kk = 0; kk < 4; kk++) {
            uint32_t qo = (uint32_t)((q0w + l15) * 144 + kk * 32 + ((lane & 16) ? 16 : 0));
            ldsm4(aQH[kk], QHa + qo);
            ldsm4(aQL[kk], QLa + qo);
        }

        int cur = 0;
        for (int kt = 0; kt < ktn; kt++) {
            if (kt + 1 < ktn) {
                char* bb = sm + OBUF + (uint32_t)(cur ^ 1) * BUFSTRIDE;
                size_t t0 = (size_t)(kt + 1) * 128 * D_;
                loadcopy(Kh + t0, bb + BKH, tid);
                loadcopy(Kl + t0, bb + BKL, tid);
                loadcopy(Vh + t0, bb + BVH, tid);
                loadcopy(Vl + t0, bb + BVL, tid);
            }
            const uint32_t KHa = BUFa + (uint32_t)cur * BUFSTRIDE;
            const uint32_t KLa = KHa + BKL;
            const uint32_t VHa = KHa + BVH;

#pragma unroll
            for (int j = 0; j < 8; j++) {
                const int ct = kt * 128 + j * 16 + 2 * lc;
                float c0[4] = {0, 0, 0, 0}, c1[4] = {0, 0, 0, 0};
                uint32_t jo = (uint32_t)j * 2304u + koff4;
#pragma unroll
                for (int kk = 0; kk < 4; kk++) {
                    uint32_t bH[4], bL[4];
                    ldsm4(bH, KHa + jo + kk * 32);
                    ldsm4(bL, KLa + jo + kk * 32);
                    mma16816(c0, aQH[kk], bH[0], bH[1]);
                    mma16816(c0, aQH[kk], bL[0], bL[1]);
                    mma16816(c0, aQL[kk], bH[0], bH[1]);
                    mma16816(c1, aQH[kk], bH[2], bH[3]);
                    mma16816(c1, aQH[kk], bL[2], bL[3]);
                    mma16816(c1, aQL[kk], bH[2], bH[3]);
                }
                bool m0 = (ct < cnt), m1 = (ct + 1 < cnt);
                bool m8 = (ct + 8 < cnt), m9 = (ct + 9 < cnt);
                float p0a0 = m0 ? __expf(c0[0] * SCALE) : 0.0f;
                float p0a1 = m1 ? __expf(c0[1] * SCALE) : 0.0f;
                float p0b0 = m0 ? __expf(c0[2] * SCALE) : 0.0f;
                float p0b1 = m1 ? __expf(c0[3] * SCALE) : 0.0f;
                float p1a0 = m8 ? __expf(c1[0] * SCALE) : 0.0f;
                float p1a1 = m9 ? __expf(c1[1] * SCALE) : 0.0f;
                float p1b0 = m8 ? __expf(c1[2] * SCALE) : 0.0f;
                float p1b1 = m9 ? __expf(c1[3] * SCALE) : 0.0f;

                lpa += (p0a0 + p0a1) + (p1a0 + p1a1);
                lpb += (p0b0 + p0b1) + (p1b0 + p1b1);

                *(float2*)(pra + ct)     = make_float2(p0a0, p0a1);
                *(float2*)(pra + ct + 8) = make_float2(p1a0, p1a1);
                *(float2*)(prb + ct)     = make_float2(p0b0, p0b1);
                *(float2*)(prb + ct + 8) = make_float2(p1b0, p1b1);

                uint32_t paH[4], paL[4];
                paH[0] = pack2(bhi(p0a0), bhi(p0a1));
                paH[1] = pack2(bhi(p0b0), bhi(p0b1));
                paH[2] = pack2(bhi(p1a0), bhi(p1a1));
                paH[3] = pack2(bhi(p1b0), bhi(p1b1));
                paL[0] = pack2(p0a0 - bhi(p0a0), p0a1 - bhi(p0a1));
                paL[1] = pack2(p0b0 - bhi(p0b0), p0b1 - bhi(p0b1));
                paL[2] = pack2(p1a0 - bhi(p1a0), p1a1 - bhi(p1a1));
                paL[3] = pack2(p1b0 - bhi(p1b0), p1b1 - bhi(p1b1));

                uint32_t vj = (uint32_t)j * 2304u + voff4;
#pragma unroll
                for (int n = 0; n < 8; n++) {
                    uint32_t v4[4];
                    ldsm4t(v4, VHa + vj + n * 16);
                    mma16816(O[n], paH, v4[0], v4[1]);
                    mma16816(O[n], paH, v4[2], v4[3]);
                    mma16816(O[n], paL, v4[0], v4[1]);
                }
            }
            __syncthreads();
            cur ^= 1;
        }
    } else {
        // ================= LOCAL (banded) =================
        unsigned int* mbS = (unsigned int*)(sm + OMB);
        const int hy = h - HG;
        const float* Kp = K + ((size_t)(b * H_ + h)) * N_ * D_;
        const float* Vp = V + ((size_t)(b * H_ + h)) * N_ * D_;
        float* prowbase = pl + ((size_t)(b * HL + hy) * N_ + q0) * N_;
        float* pra = prowbase + (size_t)(q0w + lq) * N_;
        float* prb = pra + (size_t)8 * N_;
        pra_l = pra; prb_l = prb;

        int klo = q0 - W_; if (klo < 0) klo = 0;
        int khi = q0 + 255 + W_; if (khi > N_ - 1) khi = N_ - 1;
        const int ktlo = klo >> 7, kthi = khi >> 7;
        {
            float4 z = make_float4(0.f, 0.f, 0.f, 0.f);
            for (int kt = 0; kt < 16; kt++) {
                if (kt >= ktlo && kt <= kthi) continue;
                for (int idx = tid; idx < 256 * 32; idx += 512) {
                    int r = idx >> 5, c4 = (idx & 31) << 2;
                    *(float4*)(prowbase + (size_t)r * N_ + kt * 128 + c4) = z;
                }
            }
        }

        if (tid < 64) mbS[tid] = d_mb[b * 64 + tid];
        loadsplit(Qp, QH, QL, tid, 4096);
        {
            char* bb = sm + OBUF;
            loadsplit(Kp + (size_t)ktlo * 128 * D_, (__nv_bfloat16*)(bb + BKH),
                      (__nv_bfloat16*)(bb + BKL), tid, 2048);
            loadsplit(Vp + (size_t)ktlo * 128 * D_, (__nv_bfloat16*)(bb + BVH),
                      (__nv_bfloat16*)(bb + BVL), tid, 2048);
        }
        __syncthreads();

        uint32_t aQH[4][4], aQL[4][4];
#pragma unroll
        for (int kk = 0; kk < 4; kk++) {
            uint32_t qo = (uint32_t)((q0w + l15) * 144 + kk * 32 + ((lane & 16) ? 16 : 0));
            ldsm4(aQH[kk], QHa + qo);
            ldsm4(aQL[kk], QLa + qo);
        }

        int cur = 0;
        for (int kt = ktlo; kt <= kthi; kt++) {
            if (kt < kthi) {
                char* bb = sm + OBUF + (uint32_t)(cur ^ 1) * BUFSTRIDE;
                loadsplit(Kp + (size_t)(kt + 1) * 128 * D_, (__nv_bfloat16*)(bb + BKH),
                          (__nv_bfloat16*)(bb + BKL), tid, 2048);
                loadsplit(Vp + (size_t)(kt + 1) * 128 * D_, (__nv_bfloat16*)(bb + BVH),
                          (__nv_bfloat16*)(bb + BVL), tid, 2048);
            }
            const uint32_t KHa = BUFa + (uint32_t)cur * BUFSTRIDE;
            const uint32_t KLa = KHa + BKL;
            const uint32_t VHa = KHa + BVH;

            unsigned int mw[4];
#pragma unroll
            for (int i = 0; i < 4; i++) mw[i] = mbS[kt * 4 + i];
#pragma unroll
            for (int j = 0; j < 8; j++) {
                const int k0j = kt * 128 + j * 16;
                const int ct = k0j + 2 * lc;
                if (!((k0j <= qw0 + 79) && (k0j + 15 >= qw0 - 64))) {
                    float2 z2 = make_float2(0.f, 0.f);
                    *(float2*)(pra + ct) = z2; *(float2*)(pra + ct + 8) = z2;
                    *(float2*)(prb + ct) = z2; *(float2*)(prb + ct + 8) = z2;
                    continue;
                }
                float c0[4] = {0, 0, 0, 0}, c1[4] = {0, 0, 0, 0};
                uint32_t jo = (uint32_t)j * 2304u + koff4;
#pragma unroll
                for (int kk = 0; kk < 4; kk++) {
                    uint32_t bH[4], bL[4];
                    ldsm4(bH, KHa + jo + kk * 32);
                    ldsm4(bL, KLa + jo + kk * 32);
                    mma16816(c0, aQH[kk], bH[0], bH[1]);
                    mma16816(c0, aQH[kk], bL[0], bL[1]);
                    mma16816(c0, aQL[kk], bH[0], bH[1]);
                    mma16816(c1, aQH[kk], bH[2], bH[3]);
                    mma16816(c1, aQH[kk], bL[2], bL[3]);
                    mma16816(c1, aQL[kk], bH[2], bH[3]);
                }
                unsigned int w = mw[j >> 1];
                int sh = (j & 1) * 16 + 2 * lc;
                bool m0 = (w >> sh) & 1, m1 = (w >> (sh + 1)) & 1;
                bool m8 = (w >> (sh + 8)) & 1, m9 = (w >> (sh + 9)) & 1;
                bool ba0 = ((unsigned)(ct - qa + 64) <= 128u);
                bool ba1 = ((unsigned)(ct + 1 - qa + 64) <= 128u);
                bool bb0 = ((unsigned)(ct - qb + 64) <= 128u);
                bool bb1 = ((unsigned)(ct + 1 - qb + 64) <= 128u);
                bool ba8 = ((unsigned)(ct + 8 - qa + 64) <= 128u);
                bool ba9 = ((unsigned)(ct + 9 - qa + 64) <= 128u);
                bool bb8 = ((unsigned)(ct + 8 - qb + 64) <= 128u);
                bool bb9 = ((unsigned)(ct + 9 - qb + 64) <= 128u);

                float p0a0 = (m0 && ba0) ? __expf(c0[0] * SCALE) : 0.0f;
                float p0a1 = (m1 && ba1) ? __expf(c0[1] * SCALE) : 0.0f;
                float p0b0 = (m0 && bb0) ? __expf(c0[2] * SCALE) : 0.0f;
                float p0b1 = (m1 && bb1) ? __expf(c0[3] * SCALE) : 0.0f;
                float p1a0 = (m8 && ba8) ? __expf(c1[0] * SCALE) : 0.0f;
                float p1a1 = (m9 && ba9) ? __expf(c1[1] * SCALE) : 0.0f;
                float p1b0 = (m8 && bb8) ? __expf(c1[2] * SCALE) : 0.0f;
                float p1b1 = (m9 && bb9) ? __expf(c1[3] * SCALE) : 0.0f;

                lpa += (p0a0 + p0a1) + (p1a0 + p1a1);
                lpb += (p0b0 + p0b1) + (p1b0 + p1b1);

                *(float2*)(pra + ct)     = make_float2(p0a0, p0a1);
                *(float2*)(pra + ct + 8) = make_float2(p1a0, p1a1);
                *(float2*)(prb + ct)     = make_float2(p0b0, p0b1);
                *(float2*)(prb + ct + 8) = make_float2(p1b0, p1b1);

                uint32_t paH[4], paL[4];
                paH[0] = pack2(bhi(p0a0), bhi(p0a1));
                paH[1] = pack2(bhi(p0b0), bhi(p0b1));
                paH[2] = pack2(bhi(p1a0), bhi(p1a1));
                paH[3] = pack2(bhi(p1b0), bhi(p1b1));
                paL[0] = pack2(p0a0 - bhi(p0a0), p0a1 - bhi(p0a1));
                paL[1] = pack2(p0b0 - bhi(p0b0), p0b1 - bhi(p0b1));
                paL[2] = pack2(p1a0 - bhi(p1a0), p1a1 - bhi(p1a1));
                paL[3] = pack2(p1b0 - bhi(p1b0), p1b1 - bhi(p1b1));

                uint32_t vj = (uint32_t)j * 2304u + voff4;
#pragma unroll
                for (int n = 0; n < 8; n++) {
                    uint32_t v4[4];
                    ldsm4t(v4, VHa + vj + n * 16);
                    mma16816(O[n], paH, v4[0], v4[1]);
                    mma16816(O[n], paH, v4[2], v4[3]);
                    mma16816(O[n], paL, v4[0], v4[1]);
                }
            }
            __syncthreads();
            cur ^= 1;
        }
    }

    lpa += __shfl_xor_sync(0xffffffffu, lpa, 1);
    lpa += __shfl_xor_sync(0xffffffffu, lpa, 2);
    lpb += __shfl_xor_sync(0xffffffffu, lpb, 1);
    lpb += __shfl_xor_sync(0xffffffffu, lpb, 2);
    const float invla = (lpa > 0.0f) ? 1.0f / lpa : 0.0f;
    const float invlb = (lpb > 0.0f) ? 1.0f / lpb : 0.0f;

    if (!loc && lc == 0) {
        d_linv[(b * H_ + h) * N_ + qa] = invla;
        d_linv[(b * H_ + h) * N_ + qb] = invlb;
    }

    float* oa = outp + ((size_t)(b * H_ + h) * N_ + qa) * D_;
    float* ob = outp + ((size_t)(b * H_ + h) * N_ + qb) * D_;
#pragma unroll
    for (int n = 0; n < 8; n++) {
        *(float2*)(oa + n * 8 + 2 * lc) = make_float2(O[n][0] * invla, O[n][1] * invla);
        *(float2*)(ob + n * 8 + 2 * lc) = make_float2(O[n][2] * invlb, O[n][3] * invlb);
    }

    // local heads: rescale own pl bands in place (single multiply per element)
    if (loc) {
        __syncthreads();   // fence this CTA's pl writes before read-modify-write
        int loa = qa - W_; if (loa < 0) loa = 0;
        int hia = qa + W_; if (hia > N_ - 1) hia = N_ - 1;
        for (int c = loa + lc; c <= hia; c += 4) pra_l[c] *= invla;
        int lob = qb - W_; if (lob < 0) lob = 0;
        int hib = qb + W_; if (hib > N_ - 1) hib = N_ - 1;
        for (int c = lob + lc; c <= hib; c += 4) prb_l[c] *= invlb;
    }
}

// ---------------------------------------------------------------------------
// epilogue: expand+normalize pg only (R9-style 128-thread loop)
// ---------------------------------------------------------------------------
__global__ void __launch_bounds__(128) epilogue_kernel(float* __restrict__ pg) {
    const int row = blockIdx.x;            // (b*HG + hg)*N + q
    const int b = row >> 14;
    const int hg = (row >> 11) & 7;
    const int q = row & 2047;
    const float s = d_linv[(b * H_ + hg) * N_ + q];
    const float* __restrict__ src = d_pgc + (size_t)row * N_;
    float* dst = pg + (size_t)row * N_;
    const int* __restrict__ pos = d_pos + b * N_;
#pragma unroll
    for (int c0 = threadIdx.x * 4; c0 < N_; c0 += 512) {
        int4 pp = *(const int4*)(pos + c0);
        unsigned int w = d_mb[b * 64 + (c0 >> 5)];
        int sh = c0 & 31;
        float4 o;
        o.x = ((w >> sh) & 1)       ? src[pp.x] * s : 0.0f;
        o.y = ((w >> (sh + 1)) & 1) ? src[pp.y] * s : 0.0f;
        o.z = ((w >> (sh + 2)) & 1) ? src[pp.z] * s : 0.0f;
        o.w = ((w >> (sh + 3)) & 1) ? src[pp.w] * s : 0.0f;
        *(float4*)(dst + c0) = o;
    }
}

// ---------------------------------------------------------------------------
extern "C" void kernel_launch(void* const* d_in, const int* in_sizes, int n_in,
                              void* d_out, int out_size) {
    const float* Q = (const float*)d_in[0];
    const float* K = (const float*)d_in[1];
    const float* V = (const float*)d_in[2];
    const void* mask = d_in[3];

    float* out = (float*)d_out;
    float* pg = out + (size_t)B_ * H_ * N_ * D_;
    float* pl = pg + (size_t)B_ * HG * N_ * N_;

    static int attr_set = 0;
    if (!attr_set) {
        cudaFuncSetAttribute(gattn_kernel, cudaFuncAttributeMaxDynamicSharedMemorySize, SMEM_SZ);
        attr_set = 1;
    }

    prep_mask_kernel<<<1, 256>>>(mask);
    compact_kv_kernel<<<dim3(16, HG, B_), 256>>>(K, V);

    gattn_kernel<<<dim3(N_ / 256, H_, B_), 512, SMEM_SZ>>>(Q, K, V, out, pl);

    epilogue_kernel<<<B_ * HG * N_, 128>>>(pg);
}

// round 15
// speedup vs baseline: 1.3625x; 1.0101x over previous
#include <cuda_runtime.h>
#include <cuda_bf16.h>
#include <cuda_fp16.h>
#include <stdint.h>

#define B_ 2
#define H_ 16
#define N_ 2048
#define D_ 64
#define HG 8
#define HL 8
#define W_ 64
#define SCALE 0.125f

__device__ unsigned int d_mb[B_ * 64];
__device__ float d_linv[B_ * H_ * N_];
__device__ int d_pos[B_ * N_];
__device__ int d_idx[B_ * N_];
__device__ int d_cnt[B_];
__device__ __half d_pgc[(size_t)B_ * HG * N_ * N_];
__device__ __nv_bfloat16 d_kch[(size_t)B_ * HG * N_ * D_];
__device__ __nv_bfloat16 d_kcl[(size_t)B_ * HG * N_ * D_];
__device__ __nv_bfloat16 d_vch[(size_t)B_ * HG * N_ * D_];
__device__ __nv_bfloat16 d_vcl[(size_t)B_ * HG * N_ * D_];

// ---- smem layout (bytes), 256-row CTA ----
#define OQH 0u
#define OQL 36864u
#define OBUF 73728u
#define BUFSTRIDE 73728u
#define BKH 0u
#define BKL 18432u
#define BVH 36864u
#define BVL 55296u
#define OMB 221184u
#define SMEM_SZ 221696

__device__ __forceinline__ uint32_t smem_u32(const void* p) {
    uint32_t a;
    asm("{ .reg .u64 t; cvta.to.shared.u64 t, %1; cvt.u32.u64 %0, t; }" : "=r"(a) : "l"(p));
    return a;
}
__device__ __forceinline__ void ldsm4(uint32_t a[4], uint32_t addr) {
    asm volatile("ldmatrix.sync.aligned.m8n8.x4.shared.b16 {%0,%1,%2,%3}, [%4];"
                 : "=r"(a[0]), "=r"(a[1]), "=r"(a[2]), "=r"(a[3]) : "r"(addr));
}
__device__ __forceinline__ void ldsm4t(uint32_t a[4], uint32_t addr) {
    asm volatile("ldmatrix.sync.aligned.m8n8.x4.trans.shared.b16 {%0,%1,%2,%3}, [%4];"
                 : "=r"(a[0]), "=r"(a[1]), "=r"(a[2]), "=r"(a[3]) : "r"(addr));
}
__device__ __forceinline__ void mma16816(float c[4], const uint32_t a[4], uint32_t b0, uint32_t b1) {
    asm volatile("mma.sync.aligned.m16n8k16.row.col.f32.bf16.bf16.f32 "
                 "{%0,%1,%2,%3}, {%4,%5,%6,%7}, {%8,%9}, {%0,%1,%2,%3};"
                 : "+f"(c[0]), "+f"(c[1]), "+f"(c[2]), "+f"(c[3])
                 : "r"(a[0]), "r"(a[1]), "r"(a[2]), "r"(a[3]), "r"(b0), "r"(b1));
}
__device__ __forceinline__ uint32_t pack2(float lo, float hi) {
    __nv_bfloat162 t = __floats2bfloat162_rn(lo, hi);
    return *(uint32_t*)&t;
}
__device__ __forceinline__ float bhi(float x) {
    return __bfloat162float(__float2bfloat16(x));
}
__device__ __forceinline__ void split2(float a, float b, uint32_t& hw, uint32_t& lw) {
    __nv_bfloat16 ha = __float2bfloat16(a);
    float fa = __bfloat162float(ha);
    __nv_bfloat16 hb = __float2bfloat16(b);
    float fb = __bfloat162float(hb);
    hw = (uint32_t)__bfloat16_as_ushort(ha) | ((uint32_t)__bfloat16_as_ushort(hb) << 16);
    lw = (uint32_t)__bfloat16_as_ushort(__float2bfloat16(a - fa)) |
         ((uint32_t)__bfloat16_as_ushort(__float2bfloat16(b - fb)) << 16);
}

// ---------------------------------------------------------------------------
// prep: mask dtype detect, bitmask, per-batch compaction map (block-scan)
// ---------------------------------------------------------------------------
__global__ void prep_mask_kernel(const void* __restrict__ mraw) {
    __shared__ int mode;
    __shared__ int wsum[8];
    const int t = threadIdx.x;          // 256 threads
    const int lane = t & 31, wp = t >> 5;
    if (t == 0) {
        const unsigned int* w = (const unsigned int*)mraw;
        bool ii = true, ff = true;
        for (int i = 0; i < 64; i++) {
            unsigned int v = w[i];
            if (v > 1u) ii = false;
            if (v != 0u && v != 0x3F800000u) ff = false;
        }
        mode = ii ? 1 : (ff ? 2 : 0);
    }
    __syncthreads();
    int m = mode;
    if (t < 128) {
        unsigned int w = 0;
        for (int k = 0; k < 32; k++) {
            int idx = t * 32 + k;
            int v;
            if (m == 1)      v = (((const int*)mraw)[idx] != 0);
            else if (m == 2) v = (((const float*)mraw)[idx] != 0.0f);
            else             v = (((const unsigned char*)mraw)[idx] != 0);
            if (v) w |= 1u << k;
        }
        d_mb[t] = w;
    }
    __syncthreads();
    for (int b = 0; b < B_; b++) {
        unsigned int word = d_mb[b * 64 + (t >> 2)];
        unsigned int byte = (word >> ((t & 3) * 8)) & 0xFFu;
        int cnt = __popc(byte);
        int inc = cnt;
#pragma unroll
        for (int o = 1; o < 32; o <<= 1) {
            int v = __shfl_up_sync(0xffffffffu, inc, o);
            if (lane >= o) inc += v;
        }
        if (lane == 31) wsum[wp] = inc;
        __syncthreads();
        int wbase = 0;
#pragma unroll
        for (int i = 0; i < 8; i++) wbase += (i < wp) ? wsum[i] : 0;
        int p = wbase + inc - cnt;
        if (t == 255) d_cnt[b] = wbase + inc;
        for (int k = 0; k < 8; k++) {
            int c = t * 8 + k;
            if ((byte >> k) & 1) {
                d_idx[b * N_ + p] = c;
                d_pos[b * N_ + c] = p;
                p++;
            } else {
                d_pos[b * N_ + c] = 0;
            }
        }
        __syncthreads();
    }
}

// ---------------------------------------------------------------------------
__global__ void __launch_bounds__(256) compact_kv_kernel(const float* __restrict__ K,
                                                         const float* __restrict__ V) {
    const int b = blockIdx.z, h = blockIdx.y, jt = blockIdx.x;
    const int cnt = d_cnt[b];
    const int cnt_pad = (cnt + 127) & ~127;
    const int j0 = jt * 128;
    if (j0 >= cnt_pad) return;
    const size_t obase = (size_t)(b * HG + h) * N_ * D_;
    for (int idx = threadIdx.x; idx < 128 * 16; idx += 256) {
        int r = idx >> 4, c4 = (idx & 15) << 2;
        int j = j0 + r;
        float4 kv = make_float4(0.f, 0.f, 0.f, 0.f);
        float4 vv = make_float4(0.f, 0.f, 0.f, 0.f);
        if (j < cnt) {
            int src = d_idx[b * N_ + j];
            size_t sb = ((size_t)(b * H_ + h) * N_ + src) * D_ + c4;
            kv = *(const float4*)(K + sb);
            vv = *(const float4*)(V + sb);
        }
        size_t off = obase + (size_t)j * D_ + c4;
        uint32_t h01, l01, h23, l23;
        split2(kv.x, kv.y, h01, l01); split2(kv.z, kv.w, h23, l23);
        *(uint2*)(d_kch + off) = make_uint2(h01, h23);
        *(uint2*)(d_kcl + off) = make_uint2(l01, l23);
        split2(vv.x, vv.y, h01, l01); split2(vv.z, vv.w, h23, l23);
        *(uint2*)(d_vch + off) = make_uint2(h01, h23);
        *(uint2*)(d_vcl + off) = make_uint2(l01, l23);
    }
}

__device__ __forceinline__ void loadsplit(const float* __restrict__ src,
                                          __nv_bfloat16* H, __nv_bfloat16* L,
                                          int tid, int n16) {
    for (int idx = tid; idx < n16; idx += 512) {
        int r = idx >> 4, c4 = (idx & 15) << 2;
        float4 v = *(const float4*)(src + r * D_ + c4);
        uint32_t h01, l01, h23, l23;
        split2(v.x, v.y, h01, l01);
        split2(v.z, v.w, h23, l23);
        uint32_t* hp = (uint32_t*)(H + r * 72 + c4);
        uint32_t* lp = (uint32_t*)(L + r * 72 + c4);
        hp[0] = h01; hp[1] = h23;
        lp[0] = l01; lp[1] = l23;
    }
}

__device__ __forceinline__ void loadcopy(const __nv_bfloat16* __restrict__ src,
                                         char* dst, int tid) {
    const uint4* s4 = (const uint4*)src;
    for (int idx = tid; idx < 1024; idx += 512) {
        int r = idx >> 3, c8 = idx & 7;
        uint4 v = s4[r * 8 + c8];
        *(uint4*)(dst + r * 144 + c8 * 16) = v;
    }
}

// ---------------------------------------------------------------------------
// Merged attention: blockIdx.y = head (0-7 global/compact, 8-15 local/banded)
// 256 q-rows per CTA, 512 threads, double-buffered K/V.
// Global heads store UNNORMALIZED p' as fp16 to scratch; local heads rescale
// their own pl bands in the tail.
// ---------------------------------------------------------------------------
__global__ void __launch_bounds__(512, 1)
gattn_kernel(const float* __restrict__ Q, const float* __restrict__ K,
             const float* __restrict__ V, float* __restrict__ outp,
             float* __restrict__ pl) {
    extern __shared__ char sm[];
    __nv_bfloat16* QH = (__nv_bfloat16*)(sm + OQH);
    __nv_bfloat16* QL = (__nv_bfloat16*)(sm + OQL);

    const int b = blockIdx.z, h = blockIdx.y, q0 = blockIdx.x * 256;
    const bool loc = (h >= HG);
    const int tid = threadIdx.x, wq = tid >> 5, lane = tid & 31;
    const int q0w = wq * 16;
    const int l7 = lane & 7, l8 = lane & 8, l15 = lane & 15;
    const int lq = lane >> 2, lc = lane & 3;

    const float* Qp = Q + ((size_t)(b * H_ + h) * N_ + q0) * D_;

    const uint32_t QHa = smem_u32(QH), QLa = smem_u32(QL);
    const uint32_t BUFa = smem_u32(sm + OBUF);
    const uint32_t koff4 = (uint32_t)(l7 * 144 + l8 * 2 + (lane & 16) * 72);
    const uint32_t voff4 = (uint32_t)(l15 * 144 + ((lane & 16) ? 18432u : 0u));

    const int qa = q0 + q0w + lq;
    const int qb = qa + 8;
    const int qw0 = q0 + q0w;

    float O[8][4];
#pragma unroll
    for (int n = 0; n < 8; n++)
#pragma unroll
        for (int e = 0; e < 4; e++) O[n][e] = 0.0f;
    float lpa = 0.0f, lpb = 0.0f;

    float* pra_l = 0; float* prb_l = 0;

    if (!loc) {
        // ================= GLOBAL (compacted keys) =================
        const int cnt = d_cnt[b];
        const int ktn = (cnt + 127) >> 7;
        const __nv_bfloat16* Kh = d_kch + (size_t)(b * HG + h) * N_ * D_;
        const __nv_bfloat16* Kl = d_kcl + (size_t)(b * HG + h) * N_ * D_;
        const __nv_bfloat16* Vh = d_vch + (size_t)(b * HG + h) * N_ * D_;
        const __nv_bfloat16* Vl = d_vcl + (size_t)(b * HG + h) * N_ * D_;
        __half* pra = d_pgc + ((size_t)(b * HG + h) * N_ + qa) * N_;
        __half* prb = pra + (size_t)8 * N_;

        loadsplit(Qp, QH, QL, tid, 4096);
        {
            char* bb = sm + OBUF;
            loadcopy(Kh, bb + BKH, tid);
            loadcopy(Kl, bb + BKL, tid);
            loadcopy(Vh, bb + BVH, tid);
            loadcopy(Vl, bb + BVL, tid);
        }
        __syncthreads();

        uint32_t aQH[4][4], aQL[4][4];
#pragma unroll
        for (int kk = 0; kk < 4; kk++) {
            uint32_t qo = (uint32_t)((q0w + l15) * 144 + kk * 32 + ((lane & 16) ? 16 : 0));
            ldsm4(aQH[kk], QHa + qo);
            ldsm4(aQL[kk], QLa + qo);
        }

        int cur = 0;
        for (int kt = 0; kt < ktn; kt++) {
            if (kt + 1 < ktn) {
                char* bb = sm + OBUF + (uint32_t)(cur ^ 1) * BUFSTRIDE;
                size_t t0 = (size_t)(kt + 1) * 128 * D_;
                loadcopy(Kh + t0, bb + BKH, tid);
                loadcopy(Kl + t0, bb + BKL, tid);
                loadcopy(Vh + t0, bb + BVH, tid);
                loadcopy(Vl + t0, bb + BVL, tid);
            }
            const uint32_t KHa = BUFa + (uint32_t)cur * BUFSTRIDE;
            const uint32_t KLa = KHa + BKL;
            const uint32_t VHa = KHa + BVH;

#pragma unroll
            for (int j = 0; j < 8; j++) {
                const int ct = kt * 128 + j * 16 + 2 * lc;
                float c0[4] = {0, 0, 0, 0}, c1[4] = {0, 0, 0, 0};
                uint32_t jo = (uint32_t)j * 2304u + koff4;
#pragma unroll
                for (int kk = 0; kk < 4; kk++) {
                    uint32_t bH[4], bL[4];
                    ldsm4(bH, KHa + jo + kk * 32);
                    ldsm4(bL, KLa + jo + kk * 32);
                    mma16816(c0, aQH[kk], bH[0], bH[1]);
                    mma16816(c0, aQH[kk], bL[0], bL[1]);
                    mma16816(c0, aQL[kk], bH[0], bH[1]);
                    mma16816(c1, aQH[kk], bH[2], bH[3]);
                    mma16816(c1, aQH[kk], bL[2], bL[3]);
                    mma16816(c1, aQL[kk], bH[2], bH[3]);
                }
                bool m0 = (ct < cnt), m1 = (ct + 1 < cnt);
                bool m8 = (ct + 8 < cnt), m9 = (ct + 9 < cnt);
                float p0a0 = m0 ? __expf(c0[0] * SCALE) : 0.0f;
                float p0a1 = m1 ? __expf(c0[1] * SCALE) : 0.0f;
                float p0b0 = m0 ? __expf(c0[2] * SCALE) : 0.0f;
                float p0b1 = m1 ? __expf(c0[3] * SCALE) : 0.0f;
                float p1a0 = m8 ? __expf(c1[0] * SCALE) : 0.0f;
                float p1a1 = m9 ? __expf(c1[1] * SCALE) : 0.0f;
                float p1b0 = m8 ? __expf(c1[2] * SCALE) : 0.0f;
                float p1b1 = m9 ? __expf(c1[3] * SCALE) : 0.0f;

                lpa += (p0a0 + p0a1) + (p1a0 + p1a1);
                lpb += (p0b0 + p0b1) + (p1b0 + p1b1);

                *(__half2*)(pra + ct)     = __floats2half2_rn(p0a0, p0a1);
                *(__half2*)(pra + ct + 8) = __floats2half2_rn(p1a0, p1a1);
                *(__half2*)(prb + ct)     = __floats2half2_rn(p0b0, p0b1);
                *(__half2*)(prb + ct + 8) = __floats2half2_rn(p1b0, p1b1);

                uint32_t paH[4], paL[4];
                paH[0] = pack2(bhi(p0a0), bhi(p0a1));
                paH[1] = pack2(bhi(p0b0), bhi(p0b1));
                paH[2] = pack2(bhi(p1a0), bhi(p1a1));
                paH[3] = pack2(bhi(p1b0), bhi(p1b1));
                paL[0] = pack2(p0a0 - bhi(p0a0), p0a1 - bhi(p0a1));
                paL[1] = pack2(p0b0 - bhi(p0b0), p0b1 - bhi(p0b1));
                paL[2] = pack2(p1a0 - bhi(p1a0), p1a1 - bhi(p1a1));
                paL[3] = pack2(p1b0 - bhi(p1b0), p1b1 - bhi(p1b1));

                uint32_t vj = (uint32_t)j * 2304u + voff4;
#pragma unroll
                for (int n = 0; n < 8; n++) {
                    uint32_t v4[4];
                    ldsm4t(v4, VHa + vj + n * 16);
                    mma16816(O[n], paH, v4[0], v4[1]);
                    mma16816(O[n], paH, v4[2], v4[3]);
                    mma16816(O[n], paL, v4[0], v4[1]);
                }
            }
            __syncthreads();
            cur ^= 1;
        }
    } else {
        // ================= LOCAL (banded) =================
        unsigned int* mbS = (unsigned int*)(sm + OMB);
        const int hy = h - HG;
        const float* Kp = K + ((size_t)(b * H_ + h)) * N_ * D_;
        const float* Vp = V + ((size_t)(b * H_ + h)) * N_ * D_;
        float* prowbase = pl + ((size_t)(b * HL + hy) * N_ + q0) * N_;
        float* pra = prowbase + (size_t)(q0w + lq) * N_;
        float* prb = pra + (size_t)8 * N_;
        pra_l = pra; prb_l = prb;

        int klo = q0 - W_; if (klo < 0) klo = 0;
        int khi = q0 + 255 + W_; if (khi > N_ - 1) khi = N_ - 1;
        const int ktlo = klo >> 7, kthi = khi >> 7;
        {
            float4 z = make_float4(0.f, 0.f, 0.f, 0.f);
            for (int kt = 0; kt < 16; kt++) {
                if (kt >= ktlo && kt <= kthi) continue;
                for (int idx = tid; idx < 256 * 32; idx += 512) {
                    int r = idx >> 5, c4 = (idx & 31) << 2;
                    *(float4*)(prowbase + (size_t)r * N_ + kt * 128 + c4) = z;
                }
            }
        }

        if (tid < 64) mbS[tid] = d_mb[b * 64 + tid];
        loadsplit(Qp, QH, QL, tid, 4096);
        {
            char* bb = sm + OBUF;
            loadsplit(Kp + (size_t)ktlo * 128 * D_, (__nv_bfloat16*)(bb + BKH),
                      (__nv_bfloat16*)(bb + BKL), tid, 2048);
            loadsplit(Vp + (size_t)ktlo * 128 * D_, (__nv_bfloat16*)(bb + BVH),
                      (__nv_bfloat16*)(bb + BVL), tid, 2048);
        }
        __syncthreads();

        uint32_t aQH[4][4], aQL[4][4];
#pragma unroll
        for (int kk = 0; kk < 4; kk++) {
            uint32_t qo = (uint32_t)((q0w + l15) * 144 + kk * 32 + ((lane & 16) ? 16 : 0));
            ldsm4(aQH[kk], QHa + qo);
            ldsm4(aQL[kk], QLa + qo);
        }

        int cur = 0;
        for (int kt = ktlo; kt <= kthi; kt++) {
            if (kt < kthi) {
                char* bb = sm + OBUF + (uint32_t)(cur ^ 1) * BUFSTRIDE;
                loadsplit(Kp + (size_t)(kt + 1) * 128 * D_, (__nv_bfloat16*)(bb + BKH),
                          (__nv_bfloat16*)(bb + BKL), tid, 2048);
                loadsplit(Vp + (size_t)(kt + 1) * 128 * D_, (__nv_bfloat16*)(bb + BVH),
                          (__nv_bfloat16*)(bb + BVL), tid, 2048);
            }
            const uint32_t KHa = BUFa + (uint32_t)cur * BUFSTRIDE;
            const uint32_t KLa = KHa + BKL;
            const uint32_t VHa = KHa + BVH;

            unsigned int mw[4];
#pragma unroll
            for (int i = 0; i < 4; i++) mw[i] = mbS[kt * 4 + i];
#pragma unroll
            for (int j = 0; j < 8; j++) {
                const int k0j = kt * 128 + j * 16;
                const int ct = k0j + 2 * lc;
                if (!((k0j <= qw0 + 79) && (k0j + 15 >= qw0 - 64))) {
                    float2 z2 = make_float2(0.f, 0.f);
                    *(float2*)(pra + ct) = z2; *(float2*)(pra + ct + 8) = z2;
                    *(float2*)(prb + ct) = z2; *(float2*)(prb + ct + 8) = z2;
                    continue;
                }
                float c0[4] = {0, 0, 0, 0}, c1[4] = {0, 0, 0, 0};
                uint32_t jo = (uint32_t)j * 2304u + koff4;
#pragma unroll
                for (int kk = 0; kk < 4; kk++) {
                    uint32_t bH[4], bL[4];
                    ldsm4(bH, KHa + jo + kk * 32);
                    ldsm4(bL, KLa + jo + kk * 32);
                    mma16816(c0, aQH[kk], bH[0], bH[1]);
                    mma16816(c0, aQH[kk], bL[0], bL[1]);
                    mma16816(c0, aQL[kk], bH[0], bH[1]);
                    mma16816(c1, aQH[kk], bH[2], bH[3]);
                    mma16816(c1, aQH[kk], bL[2], bL[3]);
                    mma16816(c1, aQL[kk], bH[2], bH[3]);
                }
                unsigned int w = mw[j >> 1];
                int sh = (j & 1) * 16 + 2 * lc;
                bool m0 = (w >> sh) & 1, m1 = (w >> (sh + 1)) & 1;
                bool m8 = (w >> (sh + 8)) & 1, m9 = (w >> (sh + 9)) & 1;
                bool ba0 = ((unsigned)(ct - qa + 64) <= 128u);
                bool ba1 = ((unsigned)(ct + 1 - qa + 64) <= 128u);
                bool bb0 = ((unsigned)(ct - qb + 64) <= 128u);
                bool bb1 = ((unsigned)(ct + 1 - qb + 64) <= 128u);
                bool ba8 = ((unsigned)(ct + 8 - qa + 64) <= 128u);
                bool ba9 = ((unsigned)(ct + 9 - qa + 64) <= 128u);
                bool bb8 = ((unsigned)(ct + 8 - qb + 64) <= 128u);
                bool bb9 = ((unsigned)(ct + 9 - qb + 64) <= 128u);

                float p0a0 = (m0 && ba0) ? __expf(c0[0] * SCALE) : 0.0f;
                float p0a1 = (m1 && ba1) ? __expf(c0[1] * SCALE) : 0.0f;
                float p0b0 = (m0 && bb0) ? __expf(c0[2] * SCALE) : 0.0f;
                float p0b1 = (m1 && bb1) ? __expf(c0[3] * SCALE) : 0.0f;
                float p1a0 = (m8 && ba8) ? __expf(c1[0] * SCALE) : 0.0f;
                float p1a1 = (m9 && ba9) ? __expf(c1[1] * SCALE) : 0.0f;
                float p1b0 = (m8 && bb8) ? __expf(c1[2] * SCALE) : 0.0f;
                float p1b1 = (m9 && bb9) ? __expf(c1[3] * SCALE) : 0.0f;

                lpa += (p0a0 + p0a1) + (p1a0 + p1a1);
                lpb += (p0b0 + p0b1) + (p1b0 + p1b1);

                *(float2*)(pra + ct)     = make_float2(p0a0, p0a1);
                *(float2*)(pra + ct + 8) = make_float2(p1a0, p1a1);
                *(float2*)(prb + ct)     = make_float2(p0b0, p0b1);
                *(float2*)(prb + ct + 8) = make_float2(p1b0, p1b1);

                uint32_t paH[4], paL[4];
                paH[0] = pack2(bhi(p0a0), bhi(p0a1));
                paH[1] = pack2(bhi(p0b0), bhi(p0b1));
                paH[2] = pack2(bhi(p1a0), bhi(p1a1));
                paH[3] = pack2(bhi(p1b0), bhi(p1b1));
                paL[0] = pack2(p0a0 - bhi(p0a0), p0a1 - bhi(p0a1));
                paL[1] = pack2(p0b0 - bhi(p0b0), p0b1 - bhi(p0b1));
                paL[2] = pack2(p1a0 - bhi(p1a0), p1a1 - bhi(p1a1));
                paL[3] = pack2(p1b0 - bhi(p1b0), p1b1 - bhi(p1b1));

                uint32_t vj = (uint32_t)j * 2304u + voff4;
#pragma unroll
                for (int n = 0; n < 8; n++) {
                    uint32_t v4[4];
                    ldsm4t(v4, VHa + vj + n * 16);
                    mma16816(O[n], paH, v4[0], v4[1]);
                    mma16816(O[n], paH, v4[2], v4[3]);
                    mma16816(O[n], paL, v4[0], v4[1]);
                }
            }
            __syncthreads();
            cur ^= 1;
        }
    }

    lpa += __shfl_xor_sync(0xffffffffu, lpa, 1);
    lpa += __shfl_xor_sync(0xffffffffu, lpa, 2);
    lpb += __shfl_xor_sync(0xffffffffu, lpb, 1);
    lpb += __shfl_xor_sync(0xffffffffu, lpb, 2);
    const float invla = (lpa > 0.0f) ? 1.0f / lpa : 0.0f;
    const float invlb = (lpb > 0.0f) ? 1.0f / lpb : 0.0f;

    if (!loc && lc == 0) {
        d_linv[(b * H_ + h) * N_ + qa] = invla;
        d_linv[(b * H_ + h) * N_ + qb] = invlb;
    }

    float* oa = outp + ((size_t)(b * H_ + h) * N_ + qa) * D_;
    float* ob = outp + ((size_t)(b * H_ + h) * N_ + qb) * D_;
#pragma unroll
    for (int n = 0; n < 8; n++) {
        *(float2*)(oa + n * 8 + 2 * lc) = make_float2(O[n][0] * invla, O[n][1] * invla);
        *(float2*)(ob + n * 8 + 2 * lc) = make_float2(O[n][2] * invlb, O[n][3] * invlb);
    }

    // local heads: rescale own pl bands in place (single multiply per element)
    if (loc) {
        __syncthreads();
        int loa = qa - W_; if (loa < 0) loa = 0;
        int hia = qa + W_; if (hia > N_ - 1) hia = N_ - 1;
        for (int c = loa + lc; c <= hia; c += 4) pra_l[c] *= invla;
        int lob = qb - W_; if (lob < 0) lob = 0;
        int hib = qb + W_; if (hib > N_ - 1) hib = N_ - 1;
        for (int c = lob + lc; c <= hib; c += 4) prb_l[c] *= invlb;
    }
}

// ---------------------------------------------------------------------------
// epilogue: expand+normalize pg (fp16 compact scratch -> fp32 full rows)
// ---------------------------------------------------------------------------
__global__ void __launch_bounds__(128) epilogue_kernel(float* __restrict__ pg) {
    const int row = blockIdx.x;            // (b*HG + hg)*N + q
    const int b = row >> 14;
    const int hg = (row >> 11) & 7;
    const int q = row & 2047;
    const float s = d_linv[(b * H_ + hg) * N_ + q];
    const __half* __restrict__ src = d_pgc + (size_t)row * N_;
    float* dst = pg + (size_t)row * N_;
    const int* __restrict__ pos = d_pos + b * N_;
#pragma unroll
    for (int c0 = threadIdx.x * 4; c0 < N_; c0 += 512) {
        int4 pp = *(const int4*)(pos + c0);
        unsigned int w = d_mb[b * 64 + (c0 >> 5)];
        int sh = c0 & 31;
        float4 o;
        o.x = ((w >> sh) & 1)       ? __half2float(src[pp.x]) * s : 0.0f;
        o.y = ((w >> (sh + 1)) & 1) ? __half2float(src[pp.y]) * s : 0.0f;
        o.z = ((w >> (sh + 2)) & 1) ? __half2float(src[pp.z]) * s : 0.0f;
        o.w = ((w >> (sh + 3)) & 1) ? __half2float(src[pp.w]) * s : 0.0f;
        *(float4*)(dst + c0) = o;
    }
}

// ---------------------------------------------------------------------------
extern "C" void kernel_launch(void* const* d_in, const int* in_sizes, int n_in,
                              void* d_out, int out_size) {
    const float* Q = (const float*)d_in[0];
    const float* K = (const float*)d_in[1];
    const float* V = (const float*)d_in[2];
    const void* mask = d_in[3];

    float* out = (float*)d_out;
    float* pg = out + (size_t)B_ * H_ * N_ * D_;
    float* pl = pg + (size_t)B_ * HG * N_ * N_;

    static int attr_set = 0;
    if (!attr_set) {
        cudaFuncSetAttribute(gattn_kernel, cudaFuncAttributeMaxDynamicSharedMemorySize, SMEM_SZ);
        attr_set = 1;
    }

    prep_mask_kernel<<<1, 256>>>(mask);
    compact_kv_kernel<<<dim3(16, HG, B_), 256>>>(K, V);

    gattn_kernel<<<dim3(N_ / 256, H_, B_), 512, SMEM_SZ>>>(Q, K, V, out, pl);

    epilogue_kernel<<<B_ * HG * N_, 128>>>(pg);
}

// round 16
// speedup vs baseline: 1.3629x; 1.0003x over previous
#include <cuda_runtime.h>
#include <cuda_bf16.h>
#include <cuda_fp16.h>
#include <stdint.h>

#define B_ 2
#define H_ 16
#define N_ 2048
#define D_ 64
#define HG 8
#define HL 8
#define W_ 64
#define SCALE 0.125f

__device__ unsigned int d_mb[B_ * 64];
__device__ float d_linv[B_ * H_ * N_];
__device__ int d_pos[B_ * N_];
__device__ int d_idx[B_ * N_];
__device__ int d_cnt[B_];
__device__ __half d_pgc[(size_t)B_ * HG * N_ * N_];
__device__ __nv_bfloat16 d_kch[(size_t)B_ * HG * N_ * D_];
__device__ __nv_bfloat16 d_kcl[(size_t)B_ * HG * N_ * D_];
__device__ __nv_bfloat16 d_vch[(size_t)B_ * HG * N_ * D_];
__device__ __nv_bfloat16 d_vcl[(size_t)B_ * HG * N_ * D_];

// ---- smem layout (bytes), 256-row CTA ----
#define OQH 0u
#define OQL 36864u
#define OBUF 73728u
#define BUFSTRIDE 73728u
#define BKH 0u
#define BKL 18432u
#define BVH 36864u
#define BVL 55296u
#define OMB 221184u
#define SMEM_SZ 221696

__device__ __forceinline__ uint32_t smem_u32(const void* p) {
    uint32_t a;
    asm("{ .reg .u64 t; cvta.to.shared.u64 t, %1; cvt.u32.u64 %0, t; }" : "=r"(a) : "l"(p));
    return a;
}
__device__ __forceinline__ void ldsm4(uint32_t a[4], uint32_t addr) {
    asm volatile("ldmatrix.sync.aligned.m8n8.x4.shared.b16 {%0,%1,%2,%3}, [%4];"
                 : "=r"(a[0]), "=r"(a[1]), "=r"(a[2]), "=r"(a[3]) : "r"(addr));
}
__device__ __forceinline__ void ldsm4t(uint32_t a[4], uint32_t addr) {
    asm volatile("ldmatrix.sync.aligned.m8n8.x4.trans.shared.b16 {%0,%1,%2,%3}, [%4];"
                 : "=r"(a[0]), "=r"(a[1]), "=r"(a[2]), "=r"(a[3]) : "r"(addr));
}
__device__ __forceinline__ void mma16816(float c[4], const uint32_t a[4], uint32_t b0, uint32_t b1) {
    asm volatile("mma.sync.aligned.m16n8k16.row.col.f32.bf16.bf16.f32 "
                 "{%0,%1,%2,%3}, {%4,%5,%6,%7}, {%8,%9}, {%0,%1,%2,%3};"
                 : "+f"(c[0]), "+f"(c[1]), "+f"(c[2]), "+f"(c[3])
                 : "r"(a[0]), "r"(a[1]), "r"(a[2]), "r"(a[3]), "r"(b0), "r"(b1));
}
__device__ __forceinline__ uint32_t pack2(float lo, float hi) {
    __nv_bfloat162 t = __floats2bfloat162_rn(lo, hi);
    return *(uint32_t*)&t;
}
__device__ __forceinline__ float bhi(float x) {
    return __bfloat162float(__float2bfloat16(x));
}
__device__ __forceinline__ void split2(float a, float b, uint32_t& hw, uint32_t& lw) {
    __nv_bfloat16 ha = __float2bfloat16(a);
    float fa = __bfloat162float(ha);
    __nv_bfloat16 hb = __float2bfloat16(b);
    float fb = __bfloat162float(hb);
    hw = (uint32_t)__bfloat16_as_ushort(ha) | ((uint32_t)__bfloat16_as_ushort(hb) << 16);
    lw = (uint32_t)__bfloat16_as_ushort(__float2bfloat16(a - fa)) |
         ((uint32_t)__bfloat16_as_ushort(__float2bfloat16(b - fb)) << 16);
}

// ---------------------------------------------------------------------------
// prep: mask dtype detect (parallel), bitmask, per-batch compaction map
// ---------------------------------------------------------------------------
__global__ void prep_mask_kernel(const void* __restrict__ mraw) {
    __shared__ int s_ii, s_ff;
    __shared__ int wsum[8];
    const int t = threadIdx.x;          // 256 threads
    const int lane = t & 31, wp = t >> 5;
    if (t == 0) { s_ii = 1; s_ff = 1; }
    __syncthreads();
    if (t < 64) {
        unsigned int v = ((const unsigned int*)mraw)[t];
        if (v > 1u) atomicAnd(&s_ii, 0);
        if (v != 0u && v != 0x3F800000u) atomicAnd(&s_ff, 0);
    }
    __syncthreads();
    const int m = s_ii ? 1 : (s_ff ? 2 : 0);
    if (t < 128) {
        unsigned int w = 0;
        for (int k = 0; k < 32; k++) {
            int idx = t * 32 + k;
            int v;
            if (m == 1)      v = (((const int*)mraw)[idx] != 0);
            else if (m == 2) v = (((const float*)mraw)[idx] != 0.0f);
            else             v = (((const unsigned char*)mraw)[idx] != 0);
            if (v) w |= 1u << k;
        }
        d_mb[t] = w;
    }
    __syncthreads();
    for (int b = 0; b < B_; b++) {
        unsigned int word = d_mb[b * 64 + (t >> 2)];
        unsigned int byte = (word >> ((t & 3) * 8)) & 0xFFu;
        int cnt = __popc(byte);
        int inc = cnt;
#pragma unroll
        for (int o = 1; o < 32; o <<= 1) {
            int v = __shfl_up_sync(0xffffffffu, inc, o);
            if (lane >= o) inc += v;
        }
        if (lane == 31) wsum[wp] = inc;
        __syncthreads();
        int wbase = 0;
#pragma unroll
        for (int i = 0; i < 8; i++) wbase += (i < wp) ? wsum[i] : 0;
        int p = wbase + inc - cnt;
        if (t == 255) d_cnt[b] = wbase + inc;
        for (int k = 0; k < 8; k++) {
            int c = t * 8 + k;
            if ((byte >> k) & 1) {
                d_idx[b * N_ + p] = c;
                d_pos[b * N_ + c] = p;
                p++;
            } else {
                d_pos[b * N_ + c] = 0;
            }
        }
        __syncthreads();
    }
}

// ---------------------------------------------------------------------------
__global__ void __launch_bounds__(256) compact_kv_kernel(const float* __restrict__ K,
                                                         const float* __restrict__ V) {
    const int b = blockIdx.z, h = blockIdx.y, jt = blockIdx.x;
    const int cnt = d_cnt[b];
    const int cnt_pad = (cnt + 127) & ~127;
    const int j0 = jt * 128;
    if (j0 >= cnt_pad) return;
    const size_t obase = (size_t)(b * HG + h) * N_ * D_;
    for (int idx = threadIdx.x; idx < 128 * 16; idx += 256) {
        int r = idx >> 4, c4 = (idx & 15) << 2;
        int j = j0 + r;
        float4 kv = make_float4(0.f, 0.f, 0.f, 0.f);
        float4 vv = make_float4(0.f, 0.f, 0.f, 0.f);
        if (j < cnt) {
            int src = d_idx[b * N_ + j];
            size_t sb = ((size_t)(b * H_ + h) * N_ + src) * D_ + c4;
            kv = *(const float4*)(K + sb);
            vv = *(const float4*)(V + sb);
        }
        size_t off = obase + (size_t)j * D_ + c4;
        uint32_t h01, l01, h23, l23;
        split2(kv.x, kv.y, h01, l01); split2(kv.z, kv.w, h23, l23);
        *(uint2*)(d_kch + off) = make_uint2(h01, h23);
        *(uint2*)(d_kcl + off) = make_uint2(l01, l23);
        split2(vv.x, vv.y, h01, l01); split2(vv.z, vv.w, h23, l23);
        *(uint2*)(d_vch + off) = make_uint2(h01, h23);
        *(uint2*)(d_vcl + off) = make_uint2(l01, l23);
    }
}

__device__ __forceinline__ void loadsplit(const float* __restrict__ src,
                                          __nv_bfloat16* H, __nv_bfloat16* L,
                                          int tid, int n16) {
    for (int idx = tid; idx < n16; idx += 512) {
        int r = idx >> 4, c4 = (idx & 15) << 2;
        float4 v = *(const float4*)(src + r * D_ + c4);
        uint32_t h01, l01, h23, l23;
        split2(v.x, v.y, h01, l01);
        split2(v.z, v.w, h23, l23);
        uint32_t* hp = (uint32_t*)(H + r * 72 + c4);
        uint32_t* lp = (uint32_t*)(L + r * 72 + c4);
        hp[0] = h01; hp[1] = h23;
        lp[0] = l01; lp[1] = l23;
    }
}

__device__ __forceinline__ void loadcopy(const __nv_bfloat16* __restrict__ src,
                                         char* dst, int tid) {
    const uint4* s4 = (const uint4*)src;
    for (int idx = tid; idx < 1024; idx += 512) {
        int r = idx >> 3, c8 = idx & 7;
        uint4 v = s4[r * 8 + c8];
        *(uint4*)(dst + r * 144 + c8 * 16) = v;
    }
}

// QK 6-MMA group with c0/c1 interleave (2x dependent-chain spacing)
__device__ __forceinline__ void qk6(float c0[4], float c1[4],
                                    const uint32_t aH[4], const uint32_t aL[4],
                                    const uint32_t bH[4], const uint32_t bL[4]) {
    mma16816(c0, aH, bH[0], bH[1]);
    mma16816(c1, aH, bH[2], bH[3]);
    mma16816(c0, aH, bL[0], bL[1]);
    mma16816(c1, aH, bL[2], bL[3]);
    mma16816(c0, aL, bH[0], bH[1]);
    mma16816(c1, aL, bH[2], bH[3]);
}

// ---------------------------------------------------------------------------
// Merged attention: blockIdx.y = head (0-7 global/compact, 8-15 local/banded)
// 256 q-rows per CTA, 512 threads, double-buffered K/V.
// ---------------------------------------------------------------------------
__global__ void __launch_bounds__(512, 1)
gattn_kernel(const float* __restrict__ Q, const float* __restrict__ K,
             const float* __restrict__ V, float* __restrict__ outp,
             float* __restrict__ pl) {
    extern __shared__ char sm[];
    __nv_bfloat16* QH = (__nv_bfloat16*)(sm + OQH);
    __nv_bfloat16* QL = (__nv_bfloat16*)(sm + OQL);

    const int b = blockIdx.z, h = blockIdx.y, q0 = blockIdx.x * 256;
    const bool loc = (h >= HG);
    const int tid = threadIdx.x, wq = tid >> 5, lane = tid & 31;
    const int q0w = wq * 16;
    const int l7 = lane & 7, l8 = lane & 8, l15 = lane & 15;
    const int lq = lane >> 2, lc = lane & 3;

    const float* Qp = Q + ((size_t)(b * H_ + h) * N_ + q0) * D_;

    const uint32_t QHa = smem_u32(QH), QLa = smem_u32(QL);
    const uint32_t BUFa = smem_u32(sm + OBUF);
    const uint32_t koff4 = (uint32_t)(l7 * 144 + l8 * 2 + (lane & 16) * 72);
    const uint32_t voff4 = (uint32_t)(l15 * 144 + ((lane & 16) ? 18432u : 0u));

    const int qa = q0 + q0w + lq;
    const int qb = qa + 8;
    const int qw0 = q0 + q0w;

    float O[8][4];
#pragma unroll
    for (int n = 0; n < 8; n++)
#pragma unroll
        for (int e = 0; e < 4; e++) O[n][e] = 0.0f;
    float lpa = 0.0f, lpb = 0.0f;

    float* pra_l = 0; float* prb_l = 0;

    if (!loc) {
        // ================= GLOBAL (compacted keys) =================
        const int cnt = d_cnt[b];
        const int ktn = (cnt + 127) >> 7;
        const __nv_bfloat16* Kh = d_kch + (size_t)(b * HG + h) * N_ * D_;
        const __nv_bfloat16* Kl = d_kcl + (size_t)(b * HG + h) * N_ * D_;
        const __nv_bfloat16* Vh = d_vch + (size_t)(b * HG + h) * N_ * D_;
        const __nv_bfloat16* Vl = d_vcl + (size_t)(b * HG + h) * N_ * D_;
        __half* pra = d_pgc + ((size_t)(b * HG + h) * N_ + qa) * N_;
        __half* prb = pra + (size_t)8 * N_;

        loadsplit(Qp, QH, QL, tid, 4096);
        {
            char* bb = sm + OBUF;
            loadcopy(Kh, bb + BKH, tid);
            loadcopy(Kl, bb + BKL, tid);
            loadcopy(Vh, bb + BVH, tid);
            loadcopy(Vl, bb + BVL, tid);
        }
        __syncthreads();

        uint32_t aQH[4][4], aQL[4][4];
#pragma unroll
        for (int kk = 0; kk < 4; kk++) {
            uint32_t qo = (uint32_t)((q0w + l15) * 144 + kk * 32 + ((lane & 16) ? 16 : 0));
            ldsm4(aQH[kk], QHa + qo);
            ldsm4(aQL[kk], QLa + qo);
        }

        int cur = 0;
        for (int kt = 0; kt < ktn; kt++) {
            if (kt + 1 < ktn) {
                char* bb = sm + OBUF + (uint32_t)(cur ^ 1) * BUFSTRIDE;
                size_t t0 = (size_t)(kt + 1) * 128 * D_;
                loadcopy(Kh + t0, bb + BKH, tid);
                loadcopy(Kl + t0, bb + BKL, tid);
                loadcopy(Vh + t0, bb + BVH, tid);
                loadcopy(Vl + t0, bb + BVL, tid);
            }
            const uint32_t KHa = BUFa + (uint32_t)cur * BUFSTRIDE;
            const uint32_t KLa = KHa + BKL;
            const uint32_t VHa = KHa + BVH;

#pragma unroll
            for (int j = 0; j < 8; j++) {
                const int ct = kt * 128 + j * 16 + 2 * lc;
                float c0[4] = {0, 0, 0, 0}, c1[4] = {0, 0, 0, 0};
                uint32_t jo = (uint32_t)j * 2304u + koff4;
#pragma unroll
                for (int kk = 0; kk < 4; kk++) {
                    uint32_t bH[4], bL[4];
                    ldsm4(bH, KHa + jo + kk * 32);
                    ldsm4(bL, KLa + jo + kk * 32);
                    qk6(c0, c1, aQH[kk], aQL[kk], bH, bL);
                }
                bool m0 = (ct < cnt), m1 = (ct + 1 < cnt);
                bool m8 = (ct + 8 < cnt), m9 = (ct + 9 < cnt);
                float p0a0 = m0 ? __expf(c0[0] * SCALE) : 0.0f;
                float p0a1 = m1 ? __expf(c0[1] * SCALE) : 0.0f;
                float p0b0 = m0 ? __expf(c0[2] * SCALE) : 0.0f;
                float p0b1 = m1 ? __expf(c0[3] * SCALE) : 0.0f;
                float p1a0 = m8 ? __expf(c1[0] * SCALE) : 0.0f;
                float p1a1 = m9 ? __expf(c1[1] * SCALE) : 0.0f;
                float p1b0 = m8 ? __expf(c1[2] * SCALE) : 0.0f;
                float p1b1 = m9 ? __expf(c1[3] * SCALE) : 0.0f;

                lpa += (p0a0 + p0a1) + (p1a0 + p1a1);
                lpb += (p0b0 + p0b1) + (p1b0 + p1b1);

                *(__half2*)(pra + ct)     = __floats2half2_rn(p0a0, p0a1);
                *(__half2*)(pra + ct + 8) = __floats2half2_rn(p1a0, p1a1);
                *(__half2*)(prb + ct)     = __floats2half2_rn(p0b0, p0b1);
                *(__half2*)(prb + ct + 8) = __floats2half2_rn(p1b0, p1b1);

                uint32_t paH[4], paL[4];
                paH[0] = pack2(bhi(p0a0), bhi(p0a1));
                paH[1] = pack2(bhi(p0b0), bhi(p0b1));
                paH[2] = pack2(bhi(p1a0), bhi(p1a1));
                paH[3] = pack2(bhi(p1b0), bhi(p1b1));
                paL[0] = pack2(p0a0 - bhi(p0a0), p0a1 - bhi(p0a1));
                paL[1] = pack2(p0b0 - bhi(p0b0), p0b1 - bhi(p0b1));
                paL[2] = pack2(p1a0 - bhi(p1a0), p1a1 - bhi(p1a1));
                paL[3] = pack2(p1b0 - bhi(p1b0), p1b1 - bhi(p1b1));

                uint32_t vj = (uint32_t)j * 2304u + voff4;
#pragma unroll
                for (int n = 0; n < 8; n++) {
                    uint32_t v4[4];
                    ldsm4t(v4, VHa + vj + n * 16);
                    mma16816(O[n], paH, v4[0], v4[1]);
                    mma16816(O[n], paH, v4[2], v4[3]);
                    mma16816(O[n], paL, v4[0], v4[1]);
                }
            }
            __syncthreads();
            cur ^= 1;
        }
    } else {
        // ================= LOCAL (banded) =================
        unsigned int* mbS = (unsigned int*)(sm + OMB);
        const int hy = h - HG;
        const float* Kp = K + ((size_t)(b * H_ + h)) * N_ * D_;
        const float* Vp = V + ((size_t)(b * H_ + h)) * N_ * D_;
        float* prowbase = pl + ((size_t)(b * HL + hy) * N_ + q0) * N_;
        float* pra = prowbase + (size_t)(q0w + lq) * N_;
        float* prb = pra + (size_t)8 * N_;
        pra_l = pra; prb_l = prb;

        int klo = q0 - W_; if (klo < 0) klo = 0;
        int khi = q0 + 255 + W_; if (khi > N_ - 1) khi = N_ - 1;
        const int ktlo = klo >> 7, kthi = khi >> 7;
        {
            float4 z = make_float4(0.f, 0.f, 0.f, 0.f);
            for (int kt = 0; kt < 16; kt++) {
                if (kt >= ktlo && kt <= kthi) continue;
                for (int idx = tid; idx < 256 * 32; idx += 512) {
                    int r = idx >> 5, c4 = (idx & 31) << 2;
                    *(float4*)(prowbase + (size_t)r * N_ + kt * 128 + c4) = z;
                }
            }
        }

        if (tid < 64) mbS[tid] = d_mb[b * 64 + tid];
        loadsplit(Qp, QH, QL, tid, 4096);
        {
            char* bb = sm + OBUF;
            loadsplit(Kp + (size_t)ktlo * 128 * D_, (__nv_bfloat16*)(bb + BKH),
                      (__nv_bfloat16*)(bb + BKL), tid, 2048);
            loadsplit(Vp + (size_t)ktlo * 128 * D_, (__nv_bfloat16*)(bb + BVH),
                      (__nv_bfloat16*)(bb + BVL), tid, 2048);
        }
        __syncthreads();

        uint32_t aQH[4][4], aQL[4][4];
#pragma unroll
        for (int kk = 0; kk < 4; kk++) {
            uint32_t qo = (uint32_t)((q0w + l15) * 144 + kk * 32 + ((lane & 16) ? 16 : 0));
            ldsm4(aQH[kk], QHa + qo);
            ldsm4(aQL[kk], QLa + qo);
        }

        int cur = 0;
        for (int kt = ktlo; kt <= kthi; kt++) {
            if (kt < kthi) {
                char* bb = sm + OBUF + (uint32_t)(cur ^ 1) * BUFSTRIDE;
                loadsplit(Kp + (size_t)(kt + 1) * 128 * D_, (__nv_bfloat16*)(bb + BKH),
                          (__nv_bfloat16*)(bb + BKL), tid, 2048);
                loadsplit(Vp + (size_t)(kt + 1) * 128 * D_, (__nv_bfloat16*)(bb + BVH),
                          (__nv_bfloat16*)(bb + BVL), tid, 2048);
            }
            const uint32_t KHa = BUFa + (uint32_t)cur * BUFSTRIDE;
            const uint32_t KLa = KHa + BKL;
            const uint32_t VHa = KHa + BVH;

            unsigned int mw[4];
#pragma unroll
            for (int i = 0; i < 4; i++) mw[i] = mbS[kt * 4 + i];
#pragma unroll
            for (int j = 0; j < 8; j++) {
                const int k0j = kt * 128 + j * 16;
                const int ct = k0j + 2 * lc;
                if (!((k0j <= qw0 + 79) && (k0j + 15 >= qw0 - 64))) {
                    float2 z2 = make_float2(0.f, 0.f);
                    *(float2*)(pra + ct) = z2; *(float2*)(pra + ct + 8) = z2;
                    *(float2*)(prb + ct) = z2; *(float2*)(prb + ct + 8) = z2;
                    continue;
                }
                float c0[4] = {0, 0, 0, 0}, c1[4] = {0, 0, 0, 0};
                uint32_t jo = (uint32_t)j * 2304u + koff4;
#pragma unroll
                for (int kk = 0; kk < 4; kk++) {
                    uint32_t bH[4], bL[4];
                    ldsm4(bH, KHa + jo + kk * 32);
                    ldsm4(bL, KLa + jo + kk * 32);
                    qk6(c0, c1, aQH[kk], aQL[kk], bH, bL);
                }
                unsigned int w = mw[j >> 1];
                int sh = (j & 1) * 16 + 2 * lc;
                bool m0 = (w >> sh) & 1, m1 = (w >> (sh + 1)) & 1;
                bool m8 = (w >> (sh + 8)) & 1, m9 = (w >> (sh + 9)) & 1;
                bool ba0 = ((unsigned)(ct - qa + 64) <= 128u);
                bool ba1 = ((unsigned)(ct + 1 - qa + 64) <= 128u);
                bool bb0 = ((unsigned)(ct - qb + 64) <= 128u);
                bool bb1 = ((unsigned)(ct + 1 - qb + 64) <= 128u);
                bool ba8 = ((unsigned)(ct + 8 - qa + 64) <= 128u);
                bool ba9 = ((unsigned)(ct + 9 - qa + 64) <= 128u);
                bool bb8 = ((unsigned)(ct + 8 - qb + 64) <= 128u);
                bool bb9 = ((unsigned)(ct + 9 - qb + 64) <= 128u);

                float p0a0 = (m0 && ba0) ? __expf(c0[0] * SCALE) : 0.0f;
                float p0a1 = (m1 && ba1) ? __expf(c0[1] * SCALE) : 0.0f;
                float p0b0 = (m0 && bb0) ? __expf(c0[2] * SCALE) : 0.0f;
                float p0b1 = (m1 && bb1) ? __expf(c0[3] * SCALE) : 0.0f;
                float p1a0 = (m8 && ba8) ? __expf(c1[0] * SCALE) : 0.0f;
                float p1a1 = (m9 && ba9) ? __expf(c1[1] * SCALE) : 0.0f;
                float p1b0 = (m8 && bb8) ? __expf(c1[2] * SCALE) : 0.0f;
                float p1b1 = (m9 && bb9) ? __expf(c1[3] * SCALE) : 0.0f;

                lpa += (p0a0 + p0a1) + (p1a0 + p1a1);
                lpb += (p0b0 + p0b1) + (p1b0 + p1b1);

                *(float2*)(pra + ct)     = make_float2(p0a0, p0a1);
                *(float2*)(pra + ct + 8) = make_float2(p1a0, p1a1);
                *(float2*)(prb + ct)     = make_float2(p0b0, p0b1);
                *(float2*)(prb + ct + 8) = make_float2(p1b0, p1b1);

                uint32_t paH[4], paL[4];
                paH[0] = pack2(bhi(p0a0), bhi(p0a1));
                paH[1] = pack2(bhi(p0b0), bhi(p0b1));
                paH[2] = pack2(bhi(p1a0), bhi(p1a1));
                paH[3] = pack2(bhi(p1b0), bhi(p1b1));
                paL[0] = pack2(p0a0 - bhi(p0a0), p0a1 - bhi(p0a1));
                paL[1] = pack2(p0b0 - bhi(p0b0), p0b1 - bhi(p0b1));
                paL[2] = pack2(p1a0 - bhi(p1a0), p1a1 - bhi(p1a1));
                paL[3] = pack2(p1b0 - bhi(p1b0), p1b1 - bhi(p1b1));

                uint32_t vj = (uint32_t)j * 2304u + voff4;
#pragma unroll
                for (int n = 0; n < 8; n++) {
                    uint32_t v4[4];
                    ldsm4t(v4, VHa + vj + n * 16);
                    mma16816(O[n], paH, v4[0], v4[1]);
                    mma16816(O[n], paH, v4[2], v4[3]);
                    mma16816(O[n], paL, v4[0], v4[1]);
                }
            }
            __syncthreads();
            cur ^= 1;
        }
    }

    lpa += __shfl_xor_sync(0xffffffffu, lpa, 1);
    lpa += __shfl_xor_sync(0xffffffffu, lpa, 2);
    lpb += __shfl_xor_sync(0xffffffffu, lpb, 1);
    lpb += __shfl_xor_sync(0xffffffffu, lpb, 2);
    const float invla = (lpa > 0.0f) ? 1.0f / lpa : 0.0f;
    const float invlb = (lpb > 0.0f) ? 1.0f / lpb : 0.0f;

    if (!loc && lc == 0) {
        d_linv[(b * H_ + h) * N_ + qa] = invla;
        d_linv[(b * H_ + h) * N_ + qb] = invlb;
    }

    float* oa = outp + ((size_t)(b * H_ + h) * N_ + qa) * D_;
    float* ob = outp + ((size_t)(b * H_ + h) * N_ + qb) * D_;
#pragma unroll
    for (int n = 0; n < 8; n++) {
        *(float2*)(oa + n * 8 + 2 * lc) = make_float2(O[n][0] * invla, O[n][1] * invla);
        *(float2*)(ob + n * 8 + 2 * lc) = make_float2(O[n][2] * invlb, O[n][3] * invlb);
    }

    // local heads: rescale own pl bands in place
    if (loc) {
        __syncthreads();
        int loa = qa - W_; if (loa < 0) loa = 0;
        int hia = qa + W_; if (hia > N_ - 1) hia = N_ - 1;
        for (int c = loa + lc; c <= hia; c += 4) pra_l[c] *= invla;
        int lob = qb - W_; if (lob < 0) lob = 0;
        int hib = qb + W_; if (hib > N_ - 1) hib = N_ - 1;
        for (int c = lob + lc; c <= hib; c += 4) prb_l[c] *= invlb;
    }
}

// ---------------------------------------------------------------------------
// epilogue: expand+normalize pg (fp16 compact scratch -> fp32 full rows)
// ---------------------------------------------------------------------------
__global__ void __launch_bounds__(128) epilogue_kernel(float* __restrict__ pg) {
    const int row = blockIdx.x;
    const int b = row >> 14;
    const int hg = (row >> 11) & 7;
    const int q = row & 2047;
    const float s = d_linv[(b * H_ + hg) * N_ + q];
    const __half* __restrict__ src = d_pgc + (size_t)row * N_;
    float* dst = pg + (size_t)row * N_;
    const int* __restrict__ pos = d_pos + b * N_;
#pragma unroll
    for (int c0 = threadIdx.x * 4; c0 < N_; c0 += 512) {
        int4 pp = *(const int4*)(pos + c0);
        unsigned int w = d_mb[b * 64 + (c0 >> 5)];
        int sh = c0 & 31;
        float4 o;
        o.x = ((w >> sh) & 1)       ? __half2float(src[pp.x]) * s : 0.0f;
        o.y = ((w >> (sh + 1)) & 1) ? __half2float(src[pp.y]) * s : 0.0f;
        o.z = ((w >> (sh + 2)) & 1) ? __half2float(src[pp.z]) * s : 0.0f;
        o.w = ((w >> (sh + 3)) & 1) ? __half2float(src[pp.w]) * s : 0.0f;
        *(float4*)(dst + c0) = o;
    }
}

// ---------------------------------------------------------------------------
extern "C" void kernel_launch(void* const* d_in, const int* in_sizes, int n_in,
                              void* d_out, int out_size) {
    const float* Q = (const float*)d_in[0];
    const float* K = (const float*)d_in[1];
    const float* V = (const float*)d_in[2];
    const void* mask = d_in[3];

    float* out = (float*)d_out;
    float* pg = out + (size_t)B_ * H_ * N_ * D_;
    float* pl = pg + (size_t)B_ * HG * N_ * N_;

    static int attr_set = 0;
    if (!attr_set) {
        cudaFuncSetAttribute(gattn_kernel, cudaFuncAttributeMaxDynamicSharedMemorySize, SMEM_SZ);
        attr_set = 1;
    }

    prep_mask_kernel<<<1, 256>>>(mask);
    compact_kv_kernel<<<dim3(16, HG, B_), 256>>>(K, V);

    gattn_kernel<<<dim3(N_ / 256, H_, B_), 512, SMEM_SZ>>>(Q, K, V, out, pl);

    epilogue_kernel<<<B_ * HG * N_, 128>>>(pg);
}

// round 17
// speedup vs baseline: 1.4010x; 1.0279x over previous
#include <cuda_runtime.h>
#include <cuda_bf16.h>
#include <cuda_fp16.h>
#include <stdint.h>

#define B_ 2
#define H_ 16
#define N_ 2048
#define D_ 64
#define HG 8
#define HL 8
#define W_ 64
#define SCALE 0.125f

__device__ unsigned int d_mb[B_ * 64];
__device__ float d_linv[B_ * H_ * N_];
__device__ int d_pos[B_ * N_];
__device__ int d_idx[B_ * N_];
__device__ int d_cnt[B_];
__device__ __half d_pgc[(size_t)B_ * HG * N_ * N_];
__device__ __nv_bfloat16 d_kch[(size_t)B_ * HG * N_ * D_];
__device__ __nv_bfloat16 d_kcl[(size_t)B_ * HG * N_ * D_];
__device__ __nv_bfloat16 d_vch[(size_t)B_ * HG * N_ * D_];
__device__ __nv_bfloat16 d_vcl[(size_t)B_ * HG * N_ * D_];

// ---- smem layout (bytes), 256-row CTA ----
#define OQH 0u
#define OQL 36864u
#define OBUF 73728u
#define BUFSTRIDE 73728u
#define BKH 0u
#define BKL 18432u
#define BVH 36864u
#define BVL 55296u
#define OMB 221184u
#define SMEM_SZ 221696

__device__ __forceinline__ uint32_t smem_u32(const void* p) {
    uint32_t a;
    asm("{ .reg .u64 t; cvta.to.shared.u64 t, %1; cvt.u32.u64 %0, t; }" : "=r"(a) : "l"(p));
    return a;
}
__device__ __forceinline__ void ldsm4(uint32_t a[4], uint32_t addr) {
    asm volatile("ldmatrix.sync.aligned.m8n8.x4.shared.b16 {%0,%1,%2,%3}, [%4];"
                 : "=r"(a[0]), "=r"(a[1]), "=r"(a[2]), "=r"(a[3]) : "r"(addr));
}
__device__ __forceinline__ void ldsm4t(uint32_t a[4], uint32_t addr) {
    asm volatile("ldmatrix.sync.aligned.m8n8.x4.trans.shared.b16 {%0,%1,%2,%3}, [%4];"
                 : "=r"(a[0]), "=r"(a[1]), "=r"(a[2]), "=r"(a[3]) : "r"(addr));
}
__device__ __forceinline__ void mma16816(float c[4], const uint32_t a[4], uint32_t b0, uint32_t b1) {
    asm volatile("mma.sync.aligned.m16n8k16.row.col.f32.bf16.bf16.f32 "
                 "{%0,%1,%2,%3}, {%4,%5,%6,%7}, {%8,%9}, {%0,%1,%2,%3};"
                 : "+f"(c[0]), "+f"(c[1]), "+f"(c[2]), "+f"(c[3])
                 : "r"(a[0]), "r"(a[1]), "r"(a[2]), "r"(a[3]), "r"(b0), "r"(b1));
}
__device__ __forceinline__ uint32_t pack2(float lo, float hi) {
    __nv_bfloat162 t = __floats2bfloat162_rn(lo, hi);
    return *(uint32_t*)&t;
}
__device__ __forceinline__ float bhi(float x) {
    return __bfloat162float(__float2bfloat16(x));
}
__device__ __forceinline__ void split2(float a, float b, uint32_t& hw, uint32_t& lw) {
    __nv_bfloat16 ha = __float2bfloat16(a);
    float fa = __bfloat162float(ha);
    __nv_bfloat16 hb = __float2bfloat16(b);
    float fb = __bfloat162float(hb);
    hw = (uint32_t)__bfloat16_as_ushort(ha) | ((uint32_t)__bfloat16_as_ushort(hb) << 16);
    lw = (uint32_t)__bfloat16_as_ushort(__float2bfloat16(a - fa)) |
         ((uint32_t)__bfloat16_as_ushort(__float2bfloat16(b - fb)) << 16);
}

// ---------------------------------------------------------------------------
// prep: mask dtype detect (parallel), bitmask, per-batch compaction map
// ---------------------------------------------------------------------------
__global__ void prep_mask_kernel(const void* __restrict__ mraw) {
    __shared__ int s_ii, s_ff;
    __shared__ int wsum[8];
    const int t = threadIdx.x;          // 256 threads
    const int lane = t & 31, wp = t >> 5;
    if (t == 0) { s_ii = 1; s_ff = 1; }
    __syncthreads();
    if (t < 64) {
        unsigned int v = ((const unsigned int*)mraw)[t];
        if (v > 1u) atomicAnd(&s_ii, 0);
        if (v != 0u && v != 0x3F800000u) atomicAnd(&s_ff, 0);
    }
    __syncthreads();
    const int m = s_ii ? 1 : (s_ff ? 2 : 0);
    if (t < 128) {
        unsigned int w = 0;
        for (int k = 0; k < 32; k++) {
            int idx = t * 32 + k;
            int v;
            if (m == 1)      v = (((const int*)mraw)[idx] != 0);
            else if (m == 2) v = (((const float*)mraw)[idx] != 0.0f);
            else             v = (((const unsigned char*)mraw)[idx] != 0);
            if (v) w |= 1u << k;
        }
        d_mb[t] = w;
    }
    __syncthreads();
    for (int b = 0; b < B_; b++) {
        unsigned int word = d_mb[b * 64 + (t >> 2)];
        unsigned int byte = (word >> ((t & 3) * 8)) & 0xFFu;
        int cnt = __popc(byte);
        int inc = cnt;
#pragma unroll
        for (int o = 1; o < 32; o <<= 1) {
            int v = __shfl_up_sync(0xffffffffu, inc, o);
            if (lane >= o) inc += v;
        }
        if (lane == 31) wsum[wp] = inc;
        __syncthreads();
        int wbase = 0;
#pragma unroll
        for (int i = 0; i < 8; i++) wbase += (i < wp) ? wsum[i] : 0;
        int p = wbase + inc - cnt;
        if (t == 255) d_cnt[b] = wbase + inc;
        for (int k = 0; k < 8; k++) {
            int c = t * 8 + k;
            if ((byte >> k) & 1) {
                d_idx[b * N_ + p] = c;
                d_pos[b * N_ + c] = p;
                p++;
            } else {
                d_pos[b * N_ + c] = 0;
            }
        }
        __syncthreads();
    }
}

// ---------------------------------------------------------------------------
__global__ void __launch_bounds__(256) compact_kv_kernel(const float* __restrict__ K,
                                                         const float* __restrict__ V) {
    const int b = blockIdx.z, h = blockIdx.y, jt = blockIdx.x;
    const int cnt = d_cnt[b];
    const int cnt_pad = (cnt + 127) & ~127;
    const int j0 = jt * 128;
    if (j0 >= cnt_pad) return;
    const size_t obase = (size_t)(b * HG + h) * N_ * D_;
    for (int idx = threadIdx.x; idx < 128 * 16; idx += 256) {
        int r = idx >> 4, c4 = (idx & 15) << 2;
        int j = j0 + r;
        float4 kv = make_float4(0.f, 0.f, 0.f, 0.f);
        float4 vv = make_float4(0.f, 0.f, 0.f, 0.f);
        if (j < cnt) {
            int src = d_idx[b * N_ + j];
            size_t sb = ((size_t)(b * H_ + h) * N_ + src) * D_ + c4;
            kv = *(const float4*)(K + sb);
            vv = *(const float4*)(V + sb);
        }
        size_t off = obase + (size_t)j * D_ + c4;
        uint32_t h01, l01, h23, l23;
        split2(kv.x, kv.y, h01, l01); split2(kv.z, kv.w, h23, l23);
        *(uint2*)(d_kch + off) = make_uint2(h01, h23);
        *(uint2*)(d_kcl + off) = make_uint2(l01, l23);
        split2(vv.x, vv.y, h01, l01); split2(vv.z, vv.w, h23, l23);
        *(uint2*)(d_vch + off) = make_uint2(h01, h23);
        *(uint2*)(d_vcl + off) = make_uint2(l01, l23);
    }
}

__device__ __forceinline__ void loadsplit(const float* __restrict__ src,
                                          __nv_bfloat16* H, __nv_bfloat16* L,
                                          int tid, int n16) {
    for (int idx = tid; idx < n16; idx += 512) {
        int r = idx >> 4, c4 = (idx & 15) << 2;
        float4 v = *(const float4*)(src + r * D_ + c4);
        uint32_t h01, l01, h23, l23;
        split2(v.x, v.y, h01, l01);
        split2(v.z, v.w, h23, l23);
        uint32_t* hp = (uint32_t*)(H + r * 72 + c4);
        uint32_t* lp = (uint32_t*)(L + r * 72 + c4);
        hp[0] = h01; hp[1] = h23;
        lp[0] = l01; lp[1] = l23;
    }
}

__device__ __forceinline__ void loadcopy(const __nv_bfloat16* __restrict__ src,
                                         char* dst, int tid) {
    const uint4* s4 = (const uint4*)src;
    for (int idx = tid; idx < 1024; idx += 512) {
        int r = idx >> 3, c8 = idx & 7;
        uint4 v = s4[r * 8 + c8];
        *(uint4*)(dst + r * 144 + c8 * 16) = v;
    }
}

// QK 6-MMA group with c0/c1 interleave
__device__ __forceinline__ void qk6(float c0[4], float c1[4],
                                    const uint32_t aH[4], const uint32_t aL[4],
                                    const uint32_t bH[4], const uint32_t bL[4]) {
    mma16816(c0, aH, bH[0], bH[1]);
    mma16816(c1, aH, bH[2], bH[3]);
    mma16816(c0, aH, bL[0], bL[1]);
    mma16816(c1, aH, bL[2], bL[3]);
    mma16816(c0, aL, bH[0], bH[1]);
    mma16816(c1, aL, bH[2], bH[3]);
}

// ---------------------------------------------------------------------------
// Merged attention, 1-D grid: bids [0,128) = GLOBAL CTAs (scheduled first ->
// all fit in wave 1, no SM runs two heavy CTAs), [128,256) = LOCAL CTAs.
// 256 q-rows per CTA, 512 threads, double-buffered K/V.
// ---------------------------------------------------------------------------
__global__ void __launch_bounds__(512, 1)
gattn_kernel(const float* __restrict__ Q, const float* __restrict__ K,
             const float* __restrict__ V, float* __restrict__ outp,
             float* __restrict__ pl) {
    extern __shared__ char sm[];
    __nv_bfloat16* QH = (__nv_bfloat16*)(sm + OQH);
    __nv_bfloat16* QL = (__nv_bfloat16*)(sm + OQL);

    const int bid = blockIdx.x;
    const bool loc = (bid >= 128);
    const int sub = loc ? (bid - 128) : bid;
    const int b = sub >> 6;
    const int h = ((sub >> 3) & 7) + (loc ? HG : 0);
    const int q0 = (sub & 7) * 256;

    const int tid = threadIdx.x, wq = tid >> 5, lane = tid & 31;
    const int q0w = wq * 16;
    const int l7 = lane & 7, l8 = lane & 8, l15 = lane & 15;
    const int lq = lane >> 2, lc = lane & 3;

    const float* Qp = Q + ((size_t)(b * H_ + h) * N_ + q0) * D_;

    const uint32_t QHa = smem_u32(QH), QLa = smem_u32(QL);
    const uint32_t BUFa = smem_u32(sm + OBUF);
    const uint32_t koff4 = (uint32_t)(l7 * 144 + l8 * 2 + (lane & 16) * 72);
    const uint32_t voff4 = (uint32_t)(l15 * 144 + ((lane & 16) ? 18432u : 0u));

    const int qa = q0 + q0w + lq;
    const int qb = qa + 8;
    const int qw0 = q0 + q0w;

    float O[8][4];
#pragma unroll
    for (int n = 0; n < 8; n++)
#pragma unroll
        for (int e = 0; e < 4; e++) O[n][e] = 0.0f;
    float lpa = 0.0f, lpb = 0.0f;

    float* pra_l = 0; float* prb_l = 0;

    if (!loc) {
        // ================= GLOBAL (compacted keys) =================
        const int cnt = d_cnt[b];
        const int ktn = (cnt + 127) >> 7;
        const __nv_bfloat16* Kh = d_kch + (size_t)(b * HG + h) * N_ * D_;
        const __nv_bfloat16* Kl = d_kcl + (size_t)(b * HG + h) * N_ * D_;
        const __nv_bfloat16* Vh = d_vch + (size_t)(b * HG + h) * N_ * D_;
        const __nv_bfloat16* Vl = d_vcl + (size_t)(b * HG + h) * N_ * D_;
        __half* pra = d_pgc + ((size_t)(b * HG + h) * N_ + qa) * N_;
        __half* prb = pra + (size_t)8 * N_;

        loadsplit(Qp, QH, QL, tid, 4096);
        {
            char* bb = sm + OBUF;
            loadcopy(Kh, bb + BKH, tid);
            loadcopy(Kl, bb + BKL, tid);
            loadcopy(Vh, bb + BVH, tid);
            loadcopy(Vl, bb + BVL, tid);
        }
        __syncthreads();

        uint32_t aQH[4][4], aQL[4][4];
#pragma unroll
        for (int kk = 0; kk < 4; kk++) {
            uint32_t qo = (uint32_t)((q0w + l15) * 144 + kk * 32 + ((lane & 16) ? 16 : 0));
            ldsm4(aQH[kk], QHa + qo);
            ldsm4(aQL[kk], QLa + qo);
        }

        int cur = 0;
        for (int kt = 0; kt < ktn; kt++) {
            if (kt + 1 < ktn) {
                char* bb = sm + OBUF + (uint32_t)(cur ^ 1) * BUFSTRIDE;
                size_t t0 = (size_t)(kt + 1) * 128 * D_;
                loadcopy(Kh + t0, bb + BKH, tid);
                loadcopy(Kl + t0, bb + BKL, tid);
                loadcopy(Vh + t0, bb + BVH, tid);
                loadcopy(Vl + t0, bb + BVL, tid);
            }
            const uint32_t KHa = BUFa + (uint32_t)cur * BUFSTRIDE;
            const uint32_t KLa = KHa + BKL;
            const uint32_t VHa = KHa + BVH;

#pragma unroll
            for (int j = 0; j < 8; j++) {
                const int ct = kt * 128 + j * 16 + 2 * lc;
                float c0[4] = {0, 0, 0, 0}, c1[4] = {0, 0, 0, 0};
                uint32_t jo = (uint32_t)j * 2304u + koff4;
#pragma unroll
                for (int kk = 0; kk < 4; kk++) {
                    uint32_t bH[4], bL[4];
                    ldsm4(bH, KHa + jo + kk * 32);
                    ldsm4(bL, KLa + jo + kk * 32);
                    qk6(c0, c1, aQH[kk], aQL[kk], bH, bL);
                }
                bool m0 = (ct < cnt), m1 = (ct + 1 < cnt);
                bool m8 = (ct + 8 < cnt), m9 = (ct + 9 < cnt);
                float p0a0 = m0 ? __expf(c0[0] * SCALE) : 0.0f;
                float p0a1 = m1 ? __expf(c0[1] * SCALE) : 0.0f;
                float p0b0 = m0 ? __expf(c0[2] * SCALE) : 0.0f;
                float p0b1 = m1 ? __expf(c0[3] * SCALE) : 0.0f;
                float p1a0 = m8 ? __expf(c1[0] * SCALE) : 0.0f;
                float p1a1 = m9 ? __expf(c1[1] * SCALE) : 0.0f;
                float p1b0 = m8 ? __expf(c1[2] * SCALE) : 0.0f;
                float p1b1 = m9 ? __expf(c1[3] * SCALE) : 0.0f;

                lpa += (p0a0 + p0a1) + (p1a0 + p1a1);
                lpb += (p0b0 + p0b1) + (p1b0 + p1b1);

                *(__half2*)(pra + ct)     = __floats2half2_rn(p0a0, p0a1);
                *(__half2*)(pra + ct + 8) = __floats2half2_rn(p1a0, p1a1);
                *(__half2*)(prb + ct)     = __floats2half2_rn(p0b0, p0b1);
                *(__half2*)(prb + ct + 8) = __floats2half2_rn(p1b0, p1b1);

                uint32_t paH[4], paL[4];
                paH[0] = pack2(bhi(p0a0), bhi(p0a1));
                paH[1] = pack2(bhi(p0b0), bhi(p0b1));
                paH[2] = pack2(bhi(p1a0), bhi(p1a1));
                paH[3] = pack2(bhi(p1b0), bhi(p1b1));
                paL[0] = pack2(p0a0 - bhi(p0a0), p0a1 - bhi(p0a1));
                paL[1] = pack2(p0b0 - bhi(p0b0), p0b1 - bhi(p0b1));
                paL[2] = pack2(p1a0 - bhi(p1a0), p1a1 - bhi(p1a1));
                paL[3] = pack2(p1b0 - bhi(p1b0), p1b1 - bhi(p1b1));

                uint32_t vj = (uint32_t)j * 2304u + voff4;
#pragma unroll
                for (int n = 0; n < 8; n++) {
                    uint32_t v4[4];
                    ldsm4t(v4, VHa + vj + n * 16);
                    mma16816(O[n], paH, v4[0], v4[1]);
                    mma16816(O[n], paH, v4[2], v4[3]);
                    mma16816(O[n], paL, v4[0], v4[1]);
                }
            }
            __syncthreads();
            cur ^= 1;
        }
    } else {
        // ================= LOCAL (banded) =================
        unsigned int* mbS = (unsigned int*)(sm + OMB);
        const int hy = h - HG;
        const float* Kp = K + ((size_t)(b * H_ + h)) * N_ * D_;
        const float* Vp = V + ((size_t)(b * H_ + h)) * N_ * D_;
        float* prowbase = pl + ((size_t)(b * HL + hy) * N_ + q0) * N_;
        float* pra = prowbase + (size_t)(q0w + lq) * N_;
        float* prb = pra + (size_t)8 * N_;
        pra_l = pra; prb_l = prb;

        int klo = q0 - W_; if (klo < 0) klo = 0;
        int khi = q0 + 255 + W_; if (khi > N_ - 1) khi = N_ - 1;
        const int ktlo = klo >> 7, kthi = khi >> 7;
        {
            float4 z = make_float4(0.f, 0.f, 0.f, 0.f);
            for (int kt = 0; kt < 16; kt++) {
                if (kt >= ktlo && kt <= kthi) continue;
                for (int idx = tid; idx < 256 * 32; idx += 512) {
                    int r = idx >> 5, c4 = (idx & 31) << 2;
                    *(float4*)(prowbase + (size_t)r * N_ + kt * 128 + c4) = z;
                }
            }
        }

        if (tid < 64) mbS[tid] = d_mb[b * 64 + tid];
        loadsplit(Qp, QH, QL, tid, 4096);
        {
            char* bb = sm + OBUF;
            loadsplit(Kp + (size_t)ktlo * 128 * D_, (__nv_bfloat16*)(bb + BKH),
                      (__nv_bfloat16*)(bb + BKL), tid, 2048);
            loadsplit(Vp + (size_t)ktlo * 128 * D_, (__nv_bfloat16*)(bb + BVH),
                      (__nv_bfloat16*)(bb + BVL), tid, 2048);
        }
        __syncthreads();

        uint32_t aQH[4][4], aQL[4][4];
#pragma unroll
        for (int kk = 0; kk < 4; kk++) {
            uint32_t qo = (uint32_t)((q0w + l15) * 144 + kk * 32 + ((lane & 16) ? 16 : 0));
            ldsm4(aQH[kk], QHa + qo);
            ldsm4(aQL[kk], QLa + qo);
        }

        int cur = 0;
        for (int kt = ktlo; kt <= kthi; kt++) {
            if (kt < kthi) {
                char* bb = sm + OBUF + (uint32_t)(cur ^ 1) * BUFSTRIDE;
                loadsplit(Kp + (size_t)(kt + 1) * 128 * D_, (__nv_bfloat16*)(bb + BKH),
                          (__nv_bfloat16*)(bb + BKL), tid, 2048);
                loadsplit(Vp + (size_t)(kt + 1) * 128 * D_, (__nv_bfloat16*)(bb + BVH),
                          (__nv_bfloat16*)(bb + BVL), tid, 2048);
            }
            const uint32_t KHa = BUFa + (uint32_t)cur * BUFSTRIDE;
            const uint32_t KLa = KHa + BKL;
            const uint32_t VHa = KHa + BVH;

            unsigned int mw[4];
#pragma unroll
            for (int i = 0; i < 4; i++) mw[i] = mbS[kt * 4 + i];
#pragma unroll
            for (int j = 0; j < 8; j++) {
                const int k0j = kt * 128 + j * 16;
                const int ct = k0j + 2 * lc;
                if (!((k0j <= qw0 + 79) && (k0j + 15 >= qw0 - 64))) {
                    float2 z2 = make_float2(0.f, 0.f);
                    *(float2*)(pra + ct) = z2; *(float2*)(pra + ct + 8) = z2;
                    *(float2*)(prb + ct) = z2; *(float2*)(prb + ct + 8) = z2;
                    continue;
                }
                float c0[4] = {0, 0, 0, 0}, c1[4] = {0, 0, 0, 0};
                uint32_t jo = (uint32_t)j * 2304u + koff4;
#pragma unroll
                for (int kk = 0; kk < 4; kk++) {
                    uint32_t bH[4], bL[4];
                    ldsm4(bH, KHa + jo + kk * 32);
                    ldsm4(bL, KLa + jo + kk * 32);
                    qk6(c0, c1, aQH[kk], aQL[kk], bH, bL);
                }
                unsigned int w = mw[j >> 1];
                int sh = (j & 1) * 16 + 2 * lc;
                bool m0 = (w >> sh) & 1, m1 = (w >> (sh + 1)) & 1;
                bool m8 = (w >> (sh + 8)) & 1, m9 = (w >> (sh + 9)) & 1;
                bool ba0 = ((unsigned)(ct - qa + 64) <= 128u);
                bool ba1 = ((unsigned)(ct + 1 - qa + 64) <= 128u);
                bool bb0 = ((unsigned)(ct - qb + 64) <= 128u);
                bool bb1 = ((unsigned)(ct + 1 - qb + 64) <= 128u);
                bool ba8 = ((unsigned)(ct + 8 - qa + 64) <= 128u);
                bool ba9 = ((unsigned)(ct + 9 - qa + 64) <= 128u);
                bool bb8 = ((unsigned)(ct + 8 - qb + 64) <= 128u);
                bool bb9 = ((unsigned)(ct + 9 - qb + 64) <= 128u);

                float p0a0 = (m0 && ba0) ? __expf(c0[0] * SCALE) : 0.0f;
                float p0a1 = (m1 && ba1) ? __expf(c0[1] * SCALE) : 0.0f;
                float p0b0 = (m0 && bb0) ? __expf(c0[2] * SCALE) : 0.0f;
                float p0b1 = (m1 && bb1) ? __expf(c0[3] * SCALE) : 0.0f;
                float p1a0 = (m8 && ba8) ? __expf(c1[0] * SCALE) : 0.0f;
                float p1a1 = (m9 && ba9) ? __expf(c1[1] * SCALE) : 0.0f;
                float p1b0 = (m8 && bb8) ? __expf(c1[2] * SCALE) : 0.0f;
                float p1b1 = (m9 && bb9) ? __expf(c1[3] * SCALE) : 0.0f;

                lpa += (p0a0 + p0a1) + (p1a0 + p1a1);
                lpb += (p0b0 + p0b1) + (p1b0 + p1b1);

                *(float2*)(pra + ct)     = make_float2(p0a0, p0a1);
                *(float2*)(pra + ct + 8) = make_float2(p1a0, p1a1);
                *(float2*)(prb + ct)     = make_float2(p0b0, p0b1);
                *(float2*)(prb + ct + 8) = make_float2(p1b0, p1b1);

                uint32_t paH[4], paL[4];
                paH[0] = pack2(bhi(p0a0), bhi(p0a1));
                paH[1] = pack2(bhi(p0b0), bhi(p0b1));
                paH[2] = pack2(bhi(p1a0), bhi(p1a1));
                paH[3] = pack2(bhi(p1b0), bhi(p1b1));
                paL[0] = pack2(p0a0 - bhi(p0a0), p0a1 - bhi(p0a1));
                paL[1] = pack2(p0b0 - bhi(p0b0), p0b1 - bhi(p0b1));
                paL[2] = pack2(p1a0 - bhi(p1a0), p1a1 - bhi(p1a1));
                paL[3] = pack2(p1b0 - bhi(p1b0), p1b1 - bhi(p1b1));

                uint32_t vj = (uint32_t)j * 2304u + voff4;
#pragma unroll
                for (int n = 0; n < 8; n++) {
                    uint32_t v4[4];
                    ldsm4t(v4, VHa + vj + n * 16);
                    mma16816(O[n], paH, v4[0], v4[1]);
                    mma16816(O[n], paH, v4[2], v4[3]);
                    mma16816(O[n], paL, v4[0], v4[1]);
                }
            }
            __syncthreads();
            cur ^= 1;
        }
    }

    lpa += __shfl_xor_sync(0xffffffffu, lpa, 1);
    lpa += __shfl_xor_sync(0xffffffffu, lpa, 2);
    lpb += __shfl_xor_sync(0xffffffffu, lpb, 1);
    lpb += __shfl_xor_sync(0xffffffffu, lpb, 2);
    const float invla = (lpa > 0.0f) ? 1.0f / lpa : 0.0f;
    const float invlb = (lpb > 0.0f) ? 1.0f / lpb : 0.0f;

    if (!loc && lc == 0) {
        d_linv[(b * H_ + h) * N_ + qa] = invla;
        d_linv[(b * H_ + h) * N_ + qb] = invlb;
    }

    float* oa = outp + ((size_t)(b * H_ + h) * N_ + qa) * D_;
    float* ob = outp + ((size_t)(b * H_ + h) * N_ + qb) * D_;
#pragma unroll
    for (int n = 0; n < 8; n++) {
        *(float2*)(oa + n * 8 + 2 * lc) = make_float2(O[n][0] * invla, O[n][1] * invla);
        *(float2*)(ob + n * 8 + 2 * lc) = make_float2(O[n][2] * invlb, O[n][3] * invlb);
    }

    // local heads: rescale own pl bands in place
    if (loc) {
        __syncthreads();
        int loa = qa - W_; if (loa < 0) loa = 0;
        int hia = qa + W_; if (hia > N_ - 1) hia = N_ - 1;
        for (int c = loa + lc; c <= hia; c += 4) pra_l[c] *= invla;
        int lob = qb - W_; if (lob < 0) lob = 0;
        int hib = qb + W_; if (hib > N_ - 1) hib = N_ - 1;
        for (int c = lob + lc; c <= hib; c += 4) prb_l[c] *= invlb;
    }
}

// ---------------------------------------------------------------------------
// epilogue: expand+normalize pg (fp16 compact scratch -> fp32 full rows)
// ---------------------------------------------------------------------------
__global__ void __launch_bounds__(128) epilogue_kernel(float* __restrict__ pg) {
    const int row = blockIdx.x;
    const int b = row >> 14;
    const int hg = (row >> 11) & 7;
    const int q = row & 2047;
    const float s = d_linv[(b * H_ + hg) * N_ + q];
    const __half* __restrict__ src = d_pgc + (size_t)row * N_;
    float* dst = pg + (size_t)row * N_;
    const int* __restrict__ pos = d_pos + b * N_;
#pragma unroll
    for (int c0 = threadIdx.x * 4; c0 < N_; c0 += 512) {
        int4 pp = *(const int4*)(pos + c0);
        unsigned int w = d_mb[b * 64 + (c0 >> 5)];
        int sh = c0 & 31;
        float4 o;
        o.x = ((w >> sh) & 1)       ? __half2float(src[pp.x]) * s : 0.0f;
        o.y = ((w >> (sh + 1)) & 1) ? __half2float(src[pp.y]) * s : 0.0f;
        o.z = ((w >> (sh + 2)) & 1) ? __half2float(src[pp.z]) * s : 0.0f;
        o.w = ((w >> (sh + 3)) & 1) ? __half2float(src[pp.w]) * s : 0.0f;
        *(float4*)(dst + c0) = o;
    }
}

// ---------------------------------------------------------------------------
extern "C" void kernel_launch(void* const* d_in, const int* in_sizes, int n_in,
                              void* d_out, int out_size) {
    const float* Q = (const float*)d_in[0];
    const float* K = (const float*)d_in[1];
    const float* V = (const float*)d_in[2];
    const void* mask = d_in[3];

    float* out = (float*)d_out;
    float* pg = out + (size_t)B_ * H_ * N_ * D_;
    float* pl = pg + (size_t)B_ * HG * N_ * N_;

    static int attr_set = 0;
    if (!attr_set) {
        cudaFuncSetAttribute(gattn_kernel, cudaFuncAttributeMaxDynamicSharedMemorySize, SMEM_SZ);
        attr_set = 1;
    }

    prep_mask_kernel<<<1, 256>>>(mask);
    compact_kv_kernel<<<dim3(16, HG, B_), 256>>>(K, V);

    gattn_kernel<<<256, 512, SMEM_SZ>>>(Q, K, V, out, pl);

    epilogue_kernel<<<B_ * HG * N_, 128>>>(pg);
}